// round 12
// baseline (speedup 1.0000x reference)
#include <cuda_runtime.h>
#include <cuda_bf16.h>
#include <cuda_fp16.h>
#include <math.h>
#include <stdint.h>

#define BATCH 4
#define SEQ   2048
#define DIM   1024
#define MTOT  (BATCH * SEQ)   // 8192

// ======================= device scratch (no runtime alloc) =======================
__device__ __align__(128) __nv_bfloat16 g_xhi[(size_t)MTOT * DIM];
__device__ __align__(128) __nv_bfloat16 g_xlo[(size_t)MTOT * DIM];
__device__ __align__(128) __nv_bfloat16 g_whi[3][(size_t)DIM * DIM];   // [din][dout]
__device__ __align__(128) __nv_bfloat16 g_wlo[3][(size_t)DIM * DIM];
__device__ __align__(128) __nv_bfloat16 g_qhi[(size_t)MTOT * DIM];     // [b*S][D]
__device__ __align__(128) __nv_bfloat16 g_qlo[(size_t)MTOT * DIM];
__device__ __align__(128) __nv_bfloat16 g_khiT[(size_t)MTOT * DIM];    // K^T: [b][D][S]
__device__ __align__(128) __nv_bfloat16 g_kloT[(size_t)MTOT * DIM];
__device__ __align__(128) __half        g_vh[(size_t)MTOT * DIM];         // fp16 V
__device__ __align__(128) __half        g_phi[(size_t)BATCH * SEQ * SEQ]; // unnorm probs (fp16)
__device__ __align__(128) float         g_partial[BATCH][SEQ / 128][SEQ]; // rowsum partials

// ======================= PTX helpers (arch-agnostic, sm_80-era) =======================
__device__ __forceinline__ uint32_t smem_u32(const void* p) {
    uint32_t a;
    asm("{ .reg .u64 t; cvta.to.shared.u64 t, %1; cvt.u32.u64 %0, t; }" : "=r"(a) : "l"(p));
    return a;
}
__device__ __forceinline__ void cp16(uint32_t dst, const void* src) {
    asm volatile("cp.async.cg.shared.global [%0], [%1], 16;" :: "r"(dst), "l"(src));
}
__device__ __forceinline__ void cp_commit() { asm volatile("cp.async.commit_group;"); }
template<int N>
__device__ __forceinline__ void cp_wait() { asm volatile("cp.async.wait_group %0;" :: "n"(N)); }
template<int NSTAGES>
__device__ __forceinline__ void cp_wait_stage() {
    if constexpr (NSTAGES == 2)      cp_wait<0>();
    else if constexpr (NSTAGES == 3) cp_wait<1>();
    else if constexpr (NSTAGES == 4) cp_wait<2>();
    else                             cp_wait<3>();
}

__device__ __forceinline__ void ldsm4(uint32_t* r, uint32_t a) {
    asm volatile("ldmatrix.sync.aligned.m8n8.x4.shared.b16 {%0,%1,%2,%3}, [%4];"
                 : "=r"(r[0]), "=r"(r[1]), "=r"(r[2]), "=r"(r[3]) : "r"(a));
}
__device__ __forceinline__ void ldsm4t(uint32_t* r, uint32_t a) {
    asm volatile("ldmatrix.sync.aligned.m8n8.x4.trans.shared.b16 {%0,%1,%2,%3}, [%4];"
                 : "=r"(r[0]), "=r"(r[1]), "=r"(r[2]), "=r"(r[3]) : "r"(a));
}
__device__ __forceinline__ void mma_bf16(float* c, const uint32_t* a, const uint32_t* b) {
    asm volatile(
        "mma.sync.aligned.m16n8k16.row.col.f32.bf16.bf16.f32 "
        "{%0,%1,%2,%3},{%4,%5,%6,%7},{%8,%9},{%0,%1,%2,%3};"
        : "+f"(c[0]), "+f"(c[1]), "+f"(c[2]), "+f"(c[3])
        : "r"(a[0]), "r"(a[1]), "r"(a[2]), "r"(a[3]), "r"(b[0]), "r"(b[1]));
}
__device__ __forceinline__ void mma_f16(float* c, const uint32_t* a, const uint32_t* b) {
    asm volatile(
        "mma.sync.aligned.m16n8k16.row.col.f32.f16.f16.f32 "
        "{%0,%1,%2,%3},{%4,%5,%6,%7},{%8,%9},{%0,%1,%2,%3};"
        : "+f"(c[0]), "+f"(c[1]), "+f"(c[2]), "+f"(c[3])
        : "r"(a[0]), "r"(a[1]), "r"(a[2]), "r"(a[3]), "r"(b[0]), "r"(b[1]));
}

// ======================= smem layouts =======================
// gemm3 KN stage (128x128 tile): Ahi/Alo (10240B each) + Bhi/Blo (8704B each) = 37888
// qkv / scores: 3 x 37888 = 113664 (2 CTAs/SM, measured optimum)
// pv: 4 x 18944 + 512 = 76288 (2 CTAs/SM, measured optimum from R10)
#define STAGE1_B    18944
#define PV_STAGES   4
#define SMEM1_BYTES (PV_STAGES * STAGE1_B + 512)   // 76288

__device__ __forceinline__ void st_split2_bf16(__nv_bfloat16* hi, __nv_bfloat16* lo,
                                               size_t off, float f0, float f1) {
    __nv_bfloat16 h0 = __float2bfloat16(f0), h1 = __float2bfloat16(f1);
    __nv_bfloat16 l0 = __float2bfloat16(f0 - __bfloat162float(h0));
    __nv_bfloat16 l1 = __float2bfloat16(f1 - __bfloat162float(h1));
    uint32_t hp = (uint32_t)__bfloat16_as_ushort(h0) | ((uint32_t)__bfloat16_as_ushort(h1) << 16);
    uint32_t lp = (uint32_t)__bfloat16_as_ushort(l0) | ((uint32_t)__bfloat16_as_ushort(l1) << 16);
    *reinterpret_cast<uint32_t*>(hi + off) = hp;
    *reinterpret_cast<uint32_t*>(lo + off) = lp;
}

// ======================= 3-term split-bf16 GEMM (128x128 tile, 256 thr, NSTAGES, 1 sync/chunk) =======================
// B stored [k][n] row-major (ldb = n-stride), uses ldmatrix.trans.
// Exactly one commit_group per loop iteration (empty at the tail) keeps wait<k> accounting exact.
template<int NSTAGES>
__device__ __forceinline__ void gemm3_bf16(
    const __nv_bfloat16* __restrict__ ahi, const __nv_bfloat16* __restrict__ alo, int lda,
    const __nv_bfloat16* __restrict__ bhi, const __nv_bfloat16* __restrict__ blo, int ldb,
    int nchunks, float (&acc)[4][4][4])
{
    extern __shared__ char smem[];
    const uint32_t sb = smem_u32(smem);
    const int tid = threadIdx.x;
    const int lane = tid & 31, warp = tid >> 5;
    const int wm = warp >> 2, wn = warp & 3;
    constexpr int BT = 8704;
    constexpr int STAGE = 20480 + 2 * BT;   // 37888

#pragma unroll
    for (int mi = 0; mi < 4; mi++)
#pragma unroll
        for (int ni = 0; ni < 4; ni++)
#pragma unroll
            for (int k = 0; k < 4; k++) acc[mi][ni][k] = 0.f;

    auto load_chunk = [&](int s, int c) {
        const uint32_t base = sb + (uint32_t)s * STAGE;
        const uint32_t ah = base, al = base + 10240u;
        const uint32_t bh = base + 20480u, bl = base + 20480u + (uint32_t)BT;
        int i = tid;
#pragma unroll
        for (int j = 0; j < 2; j++, i += 256) {
            {
                int row = i >> 2, cc = i & 3;
                size_t go = (size_t)row * lda + c * 32 + cc * 8;
                uint32_t so = (uint32_t)row * 80u + (uint32_t)cc * 16u;
                cp16(ah + so, ahi + go);
                cp16(al + so, alo + go);
            }
            {
                int row = i >> 4, cc = i & 15;
                size_t go = (size_t)(c * 32 + row) * ldb + cc * 8;
                uint32_t so = (uint32_t)row * 272u + (uint32_t)cc * 16u;
                cp16(bh + so, bhi + go);
                cp16(bl + so, blo + go);
            }
        }
        cp_commit();
    };

#pragma unroll
    for (int s = 0; s < NSTAGES - 1; s++)
        if (s < nchunks) load_chunk(s, s);

    for (int c = 0; c < nchunks; ++c) {
        cp_wait_stage<NSTAGES>();
        __syncthreads();
        const int cnext = c + NSTAGES - 1;
        if (cnext < nchunks) {
            int s = cnext; while (s >= NSTAGES) s -= NSTAGES;
            load_chunk(s, cnext);
        } else {
            cp_commit();
        }

        int s = c; while (s >= NSTAGES) s -= NSTAGES;
        const uint32_t base = sb + (uint32_t)s * STAGE;
        const uint32_t ah = base, al = base + 10240u;
        const uint32_t bh = base + 20480u, bl = base + 20480u + (uint32_t)BT;

#pragma unroll
        for (int ks = 0; ks < 2; ++ks) {
            uint32_t Ah[4][4], Al[4][4], Bh[4][2], Bl[4][2];
            const uint32_t ao = (uint32_t)(wm * 64 + (lane & 15)) * 80u
                              + (uint32_t)(ks * 16 + (lane >> 4) * 8) * 2u;
#pragma unroll
            for (int mi = 0; mi < 4; mi++) {
                ldsm4(Ah[mi], ah + ao + (uint32_t)(mi * 16) * 80u);
                ldsm4(Al[mi], al + ao + (uint32_t)(mi * 16) * 80u);
            }
            const uint32_t brow = (uint32_t)(ks * 16 + (lane & 15));
#pragma unroll
            for (int p = 0; p < 2; p++) {
                const uint32_t bo = brow * 272u
                    + (uint32_t)(wn * 32 + p * 16 + (lane >> 4) * 8) * 2u;
                uint32_t r[4];
                ldsm4t(r, bh + bo);
                Bh[2*p][0] = r[0]; Bh[2*p][1] = r[1];
                Bh[2*p+1][0] = r[2]; Bh[2*p+1][1] = r[3];
                ldsm4t(r, bl + bo);
                Bl[2*p][0] = r[0]; Bl[2*p][1] = r[1];
                Bl[2*p+1][0] = r[2]; Bl[2*p+1][1] = r[3];
            }
#pragma unroll
            for (int mi = 0; mi < 4; mi++)
#pragma unroll
                for (int ni = 0; ni < 4; ni++) {
                    mma_bf16(acc[mi][ni], Ah[mi], Bh[ni]);
                    mma_bf16(acc[mi][ni], Ah[mi], Bl[ni]);
                    mma_bf16(acc[mi][ni], Al[mi], Bh[ni]);
                }
        }
    }
    __syncthreads();
}

// ======================= 1-term fp16 GEMM: C = Ahi * Bhi, B in [k][n], PV_STAGES deep =======================
__device__ __forceinline__ void gemm1_f16(
    const __half* __restrict__ ahi, int lda,
    const __half* __restrict__ bhi, int ldb,
    int nchunks, float (&acc)[4][4][4])
{
    extern __shared__ char smem[];
    const uint32_t sb = smem_u32(smem);
    const int tid = threadIdx.x;
    const int lane = tid & 31, warp = tid >> 5;
    const int wm = warp >> 2, wn = warp & 3;

#pragma unroll
    for (int mi = 0; mi < 4; mi++)
#pragma unroll
        for (int ni = 0; ni < 4; ni++)
#pragma unroll
            for (int k = 0; k < 4; k++) acc[mi][ni][k] = 0.f;

    auto load_chunk = [&](int s, int c) {
        const uint32_t base = sb + (uint32_t)s * STAGE1_B;
        const uint32_t ah = base, bh = base + 10240u;
        int i = tid;
#pragma unroll
        for (int j = 0; j < 2; j++, i += 256) {
            {
                int row = i >> 2, cc = i & 3;
                size_t go = (size_t)row * lda + c * 32 + cc * 8;
                uint32_t so = (uint32_t)row * 80u + (uint32_t)cc * 16u;
                cp16(ah + so, ahi + go);
            }
            {
                int row = i >> 4, cc = i & 15;
                size_t go = (size_t)(c * 32 + row) * ldb + cc * 8;
                uint32_t so = (uint32_t)row * 272u + (uint32_t)cc * 16u;
                cp16(bh + so, bhi + go);
            }
        }
        cp_commit();
    };

#pragma unroll
    for (int s = 0; s < PV_STAGES - 1; s++)
        if (s < nchunks) load_chunk(s, s);

    for (int c = 0; c < nchunks; ++c) {
        cp_wait_stage<PV_STAGES>();
        __syncthreads();
        const int cnext = c + PV_STAGES - 1;
        if (cnext < nchunks) {
            int s = cnext; while (s >= PV_STAGES) s -= PV_STAGES;
            load_chunk(s, cnext);
        } else {
            cp_commit();
        }

        int s = c; while (s >= PV_STAGES) s -= PV_STAGES;
        const uint32_t base = sb + (uint32_t)s * STAGE1_B;
        const uint32_t ah = base, bh = base + 10240u;

#pragma unroll
        for (int ks = 0; ks < 2; ++ks) {
            uint32_t Ah[4][4], Bh[4][2];
            const uint32_t ao = (uint32_t)(wm * 64 + (lane & 15)) * 80u
                              + (uint32_t)(ks * 16 + (lane >> 4) * 8) * 2u;
#pragma unroll
            for (int mi = 0; mi < 4; mi++)
                ldsm4(Ah[mi], ah + ao + (uint32_t)(mi * 16) * 80u);
            const uint32_t brow = (uint32_t)(ks * 16 + (lane & 15));
#pragma unroll
            for (int p = 0; p < 2; p++) {
                const uint32_t bo = brow * 272u
                    + (uint32_t)(wn * 32 + p * 16 + (lane >> 4) * 8) * 2u;
                uint32_t r[4];
                ldsm4t(r, bh + bo);
                Bh[2*p][0] = r[0]; Bh[2*p][1] = r[1];
                Bh[2*p+1][0] = r[2]; Bh[2*p+1][1] = r[3];
            }
#pragma unroll
            for (int mi = 0; mi < 4; mi++)
#pragma unroll
                for (int ni = 0; ni < 4; ni++)
                    mma_f16(acc[mi][ni], Ah[mi], Bh[ni]);
        }
    }
    __syncthreads();
}

// ======================= kernel: split fp32 -> bf16 hi/lo (x + Wq + Wk + Wv) =======================
#define XN ((size_t)MTOT * DIM)          // 8388608
#define WN ((size_t)DIM * DIM)           // 1048576
__global__ __launch_bounds__(256) void split_all(const float* __restrict__ x,
                                                 const float* __restrict__ wq,
                                                 const float* __restrict__ wk,
                                                 const float* __restrict__ wv) {
    size_t i = ((size_t)blockIdx.x * 256 + threadIdx.x) * 4;
    const float* src;
    __nv_bfloat16 *hi, *lo;
    size_t off;
    if (i < XN) { src = x; off = i; hi = g_xhi; lo = g_xlo; }
    else {
        size_t j = i - XN;
        int w = (int)(j / WN);
        off = j - (size_t)w * WN;
        src = (w == 0) ? wq : (w == 1) ? wk : wv;
        hi = g_whi[w]; lo = g_wlo[w];
    }
    float4 v = *reinterpret_cast<const float4*>(src + off);
    float f[4] = {v.x, v.y, v.z, v.w};
    uint32_t hp[2], lp[2];
#pragma unroll
    for (int j = 0; j < 2; j++) {
        __nv_bfloat16 h0 = __float2bfloat16(f[2*j]),   h1 = __float2bfloat16(f[2*j+1]);
        __nv_bfloat16 l0 = __float2bfloat16(f[2*j]   - __bfloat162float(h0));
        __nv_bfloat16 l1 = __float2bfloat16(f[2*j+1] - __bfloat162float(h1));
        hp[j] = (uint32_t)__bfloat16_as_ushort(h0) | ((uint32_t)__bfloat16_as_ushort(h1) << 16);
        lp[j] = (uint32_t)__bfloat16_as_ushort(l0) | ((uint32_t)__bfloat16_as_ushort(l1) << 16);
    }
    *reinterpret_cast<uint2*>(hi + off) = make_uint2(hp[0], hp[1]);
    *reinterpret_cast<uint2*>(lo + off) = make_uint2(lp[0], lp[1]);
}

// ======================= kernel: QKV projection (128x128 tile, 256 threads, 3-stage) =======================
#define SMEM3Q_BYTES (3 * 37888)    // 113664
// K^T smem staging: 2 tiles of 128 x 136 bf16 = 34816 B each (fits in the 113664 B pipeline smem)
__global__ __launch_bounds__(256) void qkv_gemm() {
    extern __shared__ char smem[];
    const int z = blockIdx.z, m0 = blockIdx.y * 128, n0 = blockIdx.x * 128;
    float acc[4][4][4];
    gemm3_bf16<3>(g_xhi + (size_t)m0 * DIM, g_xlo + (size_t)m0 * DIM, DIM,
                  g_whi[z] + n0, g_wlo[z] + n0, DIM, DIM / 32, acc);
    const int lane = threadIdx.x & 31, warp = threadIdx.x >> 5;
    const int g = lane >> 2, t = lane & 3, wm = warp >> 2, wn = warp & 3;

    if (z == 1) {
        // K: stage split-bf16 transposed tile in smem, then coalesced 16B stores to K^T
        __nv_bfloat16* th = reinterpret_cast<__nv_bfloat16*>(smem);            // [128 d][136 s]
        __nv_bfloat16* tl = reinterpret_cast<__nv_bfloat16*>(smem + 34816);
#pragma unroll
        for (int mi = 0; mi < 4; mi++) {
            const int sl = wm * 64 + mi * 16 + g;     // local s
#pragma unroll
            for (int ni = 0; ni < 4; ni++) {
                const int dl = wn * 32 + ni * 8 + 2 * t;   // local d
#pragma unroll
                for (int e = 0; e < 4; e++) {
                    const int d = dl + (e & 1);
                    const int s = sl + (e >> 1) * 8;
                    float f = acc[mi][ni][e];
                    __nv_bfloat16 h = __float2bfloat16(f);
                    __nv_bfloat16 l = __float2bfloat16(f - __bfloat162float(h));
                    th[d * 136 + s] = h;
                    tl[d * 136 + s] = l;
                }
            }
        }
        __syncthreads();
        const int b = m0 >> 11;
        const size_t boffT = (size_t)b * DIM * SEQ;
        const int s0 = m0 & (SEQ - 1);
        for (int i = threadIdx.x; i < 128 * 16; i += 256) {
            const int d = i >> 4, c16 = i & 15;
            const size_t go = boffT + (size_t)(n0 + d) * SEQ + s0 + c16 * 8;
            *reinterpret_cast<uint4*>(g_khiT + go) =
                *reinterpret_cast<const uint4*>(th + d * 136 + c16 * 8);
            *reinterpret_cast<uint4*>(g_kloT + go) =
                *reinterpret_cast<const uint4*>(tl + d * 136 + c16 * 8);
        }
        return;
    }

#pragma unroll
    for (int mi = 0; mi < 4; mi++) {
        const int r0 = m0 + wm * 64 + mi * 16 + g;
#pragma unroll
        for (int ni = 0; ni < 4; ni++) {
            const int cc = n0 + wn * 32 + ni * 8 + 2 * t;
            if (z == 2) {
                __half h0 = __float2half_rn(acc[mi][ni][0]);
                __half h1 = __float2half_rn(acc[mi][ni][1]);
                __half h2 = __float2half_rn(acc[mi][ni][2]);
                __half h3 = __float2half_rn(acc[mi][ni][3]);
                *reinterpret_cast<uint32_t*>(g_vh + (size_t)r0 * DIM + cc) =
                    (uint32_t)__half_as_ushort(h0) | ((uint32_t)__half_as_ushort(h1) << 16);
                *reinterpret_cast<uint32_t*>(g_vh + (size_t)(r0 + 8) * DIM + cc) =
                    (uint32_t)__half_as_ushort(h2) | ((uint32_t)__half_as_ushort(h3) << 16);
            } else {
                st_split2_bf16(g_qhi, g_qlo, (size_t)r0 * DIM + cc,       acc[mi][ni][0], acc[mi][ni][1]);
                st_split2_bf16(g_qhi, g_qlo, (size_t)(r0 + 8) * DIM + cc, acc[mi][ni][2], acc[mi][ni][3]);
            }
        }
    }
}

// ======================= kernel: fused scores = exp(QK^T*scale) (causal, 3-stage KN) =======================
#define SMEM3S_BYTES (3 * 37888)    // 113664
__global__ __launch_bounds__(256) void scores_gemm() {
    if (blockIdx.x > blockIdx.y) return;     // fully-masked tile, exits immediately
    extern __shared__ char smem[];
    const int b = blockIdx.z, q0 = blockIdx.y * 128, k0 = blockIdx.x * 128;
    const size_t boff  = (size_t)b * SEQ * DIM;
    const size_t boffT = (size_t)b * DIM * SEQ;
    float acc[4][4][4];
    gemm3_bf16<3>(g_qhi + boff + (size_t)q0 * DIM, g_qlo + boff + (size_t)q0 * DIM, DIM,
                  g_khiT + boffT + k0, g_kloT + boffT + k0, SEQ,
                  DIM / 32, acc);
    const bool diag = (blockIdx.x == blockIdx.y);
    __half* ph = g_phi + (size_t)b * SEQ * SEQ;
    const int lane = threadIdx.x & 31, warp = threadIdx.x >> 5;
    const int g = lane >> 2, t = lane & 3, wm = warp >> 2, wn = warp & 3;
    const float scale = 0.03125f;

    float* red = reinterpret_cast<float*>(smem);
    float rs0[4], rs1[4];
#pragma unroll
    for (int mi = 0; mi < 4; mi++) { rs0[mi] = 0.f; rs1[mi] = 0.f; }

#pragma unroll
    for (int mi = 0; mi < 4; mi++) {
        const int r0 = q0 + wm * 64 + mi * 16 + g;
#pragma unroll
        for (int ni = 0; ni < 4; ni++) {
            const int cc = k0 + wn * 32 + ni * 8 + 2 * t;
            float e0 = __expf(acc[mi][ni][0] * scale);
            float e1 = __expf(acc[mi][ni][1] * scale);
            float e2 = __expf(acc[mi][ni][2] * scale);
            float e3 = __expf(acc[mi][ni][3] * scale);
            if (diag) {
                if (cc     > r0)     e0 = 0.f;
                if (cc + 1 > r0)     e1 = 0.f;
                if (cc     > r0 + 8) e2 = 0.f;
                if (cc + 1 > r0 + 8) e3 = 0.f;
            }
            __half p0 = __float2half_rn(e0), p1 = __float2half_rn(e1);
            __half p2 = __float2half_rn(e2), p3 = __float2half_rn(e3);
            *reinterpret_cast<uint32_t*>(ph + (size_t)r0 * SEQ + cc) =
                (uint32_t)__half_as_ushort(p0) | ((uint32_t)__half_as_ushort(p1) << 16);
            *reinterpret_cast<uint32_t*>(ph + (size_t)(r0 + 8) * SEQ + cc) =
                (uint32_t)__half_as_ushort(p2) | ((uint32_t)__half_as_ushort(p3) << 16);
            rs0[mi] += e0 + e1;
            rs1[mi] += e2 + e3;
        }
    }
#pragma unroll
    for (int mi = 0; mi < 4; mi++) {
        float s0 = rs0[mi], s1 = rs1[mi];
        s0 += __shfl_xor_sync(0xFFFFFFFFu, s0, 1);
        s0 += __shfl_xor_sync(0xFFFFFFFFu, s0, 2);
        s1 += __shfl_xor_sync(0xFFFFFFFFu, s1, 1);
        s1 += __shfl_xor_sync(0xFFFFFFFFu, s1, 2);
        if (t == 0) {
            const int lr = wm * 64 + mi * 16 + g;
            red[wn * 128 + lr]     = s0;
            red[wn * 128 + lr + 8] = s1;
        }
    }
    __syncthreads();
    if (threadIdx.x < 128) {
        float tot = red[threadIdx.x] + red[128 + threadIdx.x]
                  + red[256 + threadIdx.x] + red[384 + threadIdx.x];
        g_partial[b][blockIdx.x][q0 + threadIdx.x] = tot;
    }
}

// ======================= kernel: O = (P @ V) * rsuminv (fused rowsum, heavy-first order) =======================
__global__ __launch_bounds__(256) void pv_gemm(float* __restrict__ outp) {
    extern __shared__ char smem[];
    const int b = blockIdx.z, n0 = blockIdx.x * 128;
    const int qy = (int)gridDim.y - 1 - (int)blockIdx.y;   // heavy q-tiles launch first
    const int q0 = qy * 128;

    // prologue: per-row 1/rowsum into smem beyond the pipeline buffers
    float* rsinv = reinterpret_cast<float*>(smem + PV_STAGES * STAGE1_B);
    if (threadIdx.x < 128) {
        const int q = q0 + threadIdx.x;
        const int nt = (q0 >> 7) + 1;
        float s = 0.f;
        for (int j = 0; j < nt; j++) s += g_partial[b][j][q];
        rsinv[threadIdx.x] = 1.f / s;
    }

    float acc[4][4][4];
    gemm1_f16(g_phi + (size_t)b * SEQ * SEQ + (size_t)q0 * SEQ, SEQ,
              g_vh + (size_t)b * SEQ * DIM + n0, DIM,
              (q0 + 128) / 32, acc);   // ends with __syncthreads -> rsinv visible
    float* out = outp + (size_t)b * SEQ * DIM;
    const int lane = threadIdx.x & 31, warp = threadIdx.x >> 5;
    const int g = lane >> 2, t = lane & 3, wm = warp >> 2, wn = warp & 3;
#pragma unroll
    for (int mi = 0; mi < 4; mi++) {
        const int lr = wm * 64 + mi * 16 + g;
        const int r0 = q0 + lr;
        const float i0 = rsinv[lr], i1 = rsinv[lr + 8];
#pragma unroll
        for (int ni = 0; ni < 4; ni++) {
            const int cc = n0 + wn * 32 + ni * 8 + 2 * t;
            *reinterpret_cast<float2*>(out + (size_t)r0 * DIM + cc) =
                make_float2(acc[mi][ni][0] * i0, acc[mi][ni][1] * i0);
            *reinterpret_cast<float2*>(out + (size_t)(r0 + 8) * DIM + cc) =
                make_float2(acc[mi][ni][2] * i1, acc[mi][ni][3] * i1);
        }
    }
}

// ======================= launch =======================
extern "C" void kernel_launch(void* const* d_in, const int* in_sizes, int n_in,
                              void* d_out, int out_size) {
    const float* x  = (const float*)d_in[0];
    const float* Wq = (const float*)d_in[1];
    const float* Wk = (const float*)d_in[2];
    const float* Wv = (const float*)d_in[3];
    float* out = (float*)d_out;

    cudaFuncSetAttribute(qkv_gemm,    cudaFuncAttributeMaxDynamicSharedMemorySize, SMEM3Q_BYTES);
    cudaFuncSetAttribute(scores_gemm, cudaFuncAttributeMaxDynamicSharedMemorySize, SMEM3S_BYTES);
    cudaFuncSetAttribute(pv_gemm,     cudaFuncAttributeMaxDynamicSharedMemorySize, SMEM1_BYTES);

    const size_t total = XN + 3 * WN;
    split_all<<<(unsigned)(total / 1024), 256>>>(x, Wq, Wk, Wv);

    qkv_gemm<<<dim3(DIM / 128, MTOT / 128, 3), 256, SMEM3Q_BYTES>>>();
    scores_gemm<<<dim3(SEQ / 128, SEQ / 128, BATCH), 256, SMEM3S_BYTES>>>();
    pv_gemm<<<dim3(DIM / 128, SEQ / 128, BATCH), 256, SMEM1_BYTES>>>(out);
}

// round 13
// speedup vs baseline: 1.1629x; 1.1629x over previous
#include <cuda_runtime.h>
#include <cuda_fp16.h>
#include <math.h>
#include <stdint.h>

#define BATCH 4
#define SEQ   2048
#define DIM   1024
#define MTOT  (BATCH * SEQ)   // 8192

// ======================= device scratch (no runtime alloc) =======================
__device__ __align__(128) __half g_xhi[(size_t)MTOT * DIM];
__device__ __align__(128) __half g_xlo[(size_t)MTOT * DIM];
__device__ __align__(128) __half g_whi[3][(size_t)DIM * DIM];   // [din][dout]
__device__ __align__(128) __half g_wlo[3][(size_t)DIM * DIM];
__device__ __align__(128) __half g_qhi[(size_t)MTOT * DIM];     // Q split fp16
__device__ __align__(128) __half g_qlo[(size_t)MTOT * DIM];
__device__ __align__(128) __half g_khi[(size_t)MTOT * DIM];     // K fp16 (hi only)
__device__ __align__(128) __half g_vh[(size_t)MTOT * DIM];      // V fp16 (hi only)
__device__ __align__(128) __half g_phi[(size_t)BATCH * SEQ * SEQ]; // unnorm probs
__device__ __align__(128) float  g_partial[BATCH][SEQ / 128][SEQ]; // rowsum partials

// ======================= PTX helpers (arch-agnostic, sm_80-era) =======================
__device__ __forceinline__ uint32_t smem_u32(const void* p) {
    uint32_t a;
    asm("{ .reg .u64 t; cvta.to.shared.u64 t, %1; cvt.u32.u64 %0, t; }" : "=r"(a) : "l"(p));
    return a;
}
__device__ __forceinline__ void cp16(uint32_t dst, const void* src) {
    asm volatile("cp.async.cg.shared.global [%0], [%1], 16;" :: "r"(dst), "l"(src));
}
__device__ __forceinline__ void cp_commit() { asm volatile("cp.async.commit_group;"); }
template<int N>
__device__ __forceinline__ void cp_wait() { asm volatile("cp.async.wait_group %0;" :: "n"(N)); }
template<int NSTAGES>
__device__ __forceinline__ void cp_wait_stage() {
    if constexpr (NSTAGES == 2)      cp_wait<0>();
    else if constexpr (NSTAGES == 3) cp_wait<1>();
    else                             cp_wait<2>();
}

__device__ __forceinline__ void ldsm4(uint32_t* r, uint32_t a) {
    asm volatile("ldmatrix.sync.aligned.m8n8.x4.shared.b16 {%0,%1,%2,%3}, [%4];"
                 : "=r"(r[0]), "=r"(r[1]), "=r"(r[2]), "=r"(r[3]) : "r"(a));
}
__device__ __forceinline__ void ldsm4t(uint32_t* r, uint32_t a) {
    asm volatile("ldmatrix.sync.aligned.m8n8.x4.trans.shared.b16 {%0,%1,%2,%3}, [%4];"
                 : "=r"(r[0]), "=r"(r[1]), "=r"(r[2]), "=r"(r[3]) : "r"(a));
}
__device__ __forceinline__ void mma_f16(float* c, const uint32_t* a, const uint32_t* b) {
    asm volatile(
        "mma.sync.aligned.m16n8k16.row.col.f32.f16.f16.f32 "
        "{%0,%1,%2,%3},{%4,%5,%6,%7},{%8,%9},{%0,%1,%2,%3};"
        : "+f"(c[0]), "+f"(c[1]), "+f"(c[2]), "+f"(c[3])
        : "r"(a[0]), "r"(a[1]), "r"(a[2]), "r"(a[3]), "r"(b[0]), "r"(b[1]));
}

// ======================= smem layouts =======================
// Stage = A(hi,lo: 2 x 10240) + B(hi [, lo]): BT = 8704 (KN, ldsm.trans) / 10240 (NK, ldsm)
// qkv QK (HAS_BLO, KN):  37888/stage, 3 stages = 113664 (2 CTAs/SM, proven)
// qkv V  (no BLO, KN):   29184/stage, fits in same alloc
// scores (no BLO, NK):   30720/stage, 3 stages = 92160 (2 CTAs/SM)
// pv (1-term):           18944/stage, 4 stages + 512 = 76288 (2 CTAs/SM, R10 optimum)
#define STAGE1_B    18944
#define PV_STAGES   4
#define SMEM1_BYTES (PV_STAGES * STAGE1_B + 512)   // 76288
#define SMEM3Q_BYTES (3 * 37888)                   // 113664
#define SMEMS_BYTES  (3 * 30720)                   // 92160

__device__ __forceinline__ void st_split2_f16(__half* hi, __half* lo,
                                              size_t off, float f0, float f1) {
    __half h0 = __float2half_rn(f0), h1 = __float2half_rn(f1);
    __half l0 = __float2half_rn(f0 - __half2float(h0));
    __half l1 = __float2half_rn(f1 - __half2float(h1));
    uint32_t hp = (uint32_t)__half_as_ushort(h0) | ((uint32_t)__half_as_ushort(h1) << 16);
    uint32_t lp = (uint32_t)__half_as_ushort(l0) | ((uint32_t)__half_as_ushort(l1) << 16);
    *reinterpret_cast<uint32_t*>(hi + off) = hp;
    *reinterpret_cast<uint32_t*>(lo + off) = lp;
}

// ======================= split-fp16 GEMM (128x128 tile, 256 thr, NSTAGES, 1 sync/chunk) =======================
// acc += Ahi*Bhi + Alo*Bhi (+ Ahi*Blo if HAS_BLO).
// BKN=true : B stored [k][n] row-major (ldb=n-stride), ldmatrix.trans
// BKN=false: B stored [n][k] row-major (ldb=k-stride), ldmatrix
// One commit_group per loop iteration (empty at the tail) keeps wait<k> accounting exact.
template<bool HAS_BLO, bool BKN, int NSTAGES>
__device__ __forceinline__ void gemm_f16s(
    const __half* __restrict__ ahi, const __half* __restrict__ alo, int lda,
    const __half* __restrict__ bhi, const __half* __restrict__ blo, int ldb,
    int nchunks, float (&acc)[4][4][4])
{
    extern __shared__ char smem[];
    const uint32_t sb = smem_u32(smem);
    const int tid = threadIdx.x;
    const int lane = tid & 31, warp = tid >> 5;
    const int wm = warp >> 2, wn = warp & 3;
    constexpr int BT = BKN ? 8704 : 10240;
    constexpr int STAGE = 20480 + (HAS_BLO ? 2 : 1) * BT;

#pragma unroll
    for (int mi = 0; mi < 4; mi++)
#pragma unroll
        for (int ni = 0; ni < 4; ni++)
#pragma unroll
            for (int k = 0; k < 4; k++) acc[mi][ni][k] = 0.f;

    auto load_chunk = [&](int s, int c) {
        const uint32_t base = sb + (uint32_t)s * STAGE;
        const uint32_t ah = base, al = base + 10240u;
        const uint32_t bh = base + 20480u, bl = base + 20480u + (uint32_t)BT;
        int i = tid;
#pragma unroll
        for (int j = 0; j < 2; j++, i += 256) {
            {
                int row = i >> 2, cc = i & 3;
                size_t go = (size_t)row * lda + c * 32 + cc * 8;
                uint32_t so = (uint32_t)row * 80u + (uint32_t)cc * 16u;
                cp16(ah + so, ahi + go);
                cp16(al + so, alo + go);
            }
            if (BKN) {
                int row = i >> 4, cc = i & 15;
                size_t go = (size_t)(c * 32 + row) * ldb + cc * 8;
                uint32_t so = (uint32_t)row * 272u + (uint32_t)cc * 16u;
                cp16(bh + so, bhi + go);
                if constexpr (HAS_BLO) cp16(bl + so, blo + go);
            } else {
                int row = i >> 2, cc = i & 3;
                size_t go = (size_t)row * ldb + c * 32 + cc * 8;
                uint32_t so = (uint32_t)row * 80u + (uint32_t)cc * 16u;
                cp16(bh + so, bhi + go);
                if constexpr (HAS_BLO) cp16(bl + so, blo + go);
            }
        }
        cp_commit();
    };

#pragma unroll
    for (int s = 0; s < NSTAGES - 1; s++)
        if (s < nchunks) load_chunk(s, s);

    for (int c = 0; c < nchunks; ++c) {
        cp_wait_stage<NSTAGES>();
        __syncthreads();
        const int cnext = c + NSTAGES - 1;
        if (cnext < nchunks) {
            int s = cnext; while (s >= NSTAGES) s -= NSTAGES;
            load_chunk(s, cnext);
        } else {
            cp_commit();
        }

        int s = c; while (s >= NSTAGES) s -= NSTAGES;
        const uint32_t base = sb + (uint32_t)s * STAGE;
        const uint32_t ah = base, al = base + 10240u;
        const uint32_t bh = base + 20480u, bl = base + 20480u + (uint32_t)BT;

#pragma unroll
        for (int ks = 0; ks < 2; ++ks) {
            uint32_t Ah[4][4], Al[4][4], Bh[4][2], Bl[4][2];
            const uint32_t ao = (uint32_t)(wm * 64 + (lane & 15)) * 80u
                              + (uint32_t)(ks * 16 + (lane >> 4) * 8) * 2u;
#pragma unroll
            for (int mi = 0; mi < 4; mi++) {
                ldsm4(Ah[mi], ah + ao + (uint32_t)(mi * 16) * 80u);
                ldsm4(Al[mi], al + ao + (uint32_t)(mi * 16) * 80u);
            }
            if (BKN) {
                const uint32_t brow = (uint32_t)(ks * 16 + (lane & 15));
#pragma unroll
                for (int p = 0; p < 2; p++) {
                    const uint32_t bo = brow * 272u
                        + (uint32_t)(wn * 32 + p * 16 + (lane >> 4) * 8) * 2u;
                    uint32_t r[4];
                    ldsm4t(r, bh + bo);
                    Bh[2*p][0] = r[0]; Bh[2*p][1] = r[1];
                    Bh[2*p+1][0] = r[2]; Bh[2*p+1][1] = r[3];
                    if constexpr (HAS_BLO) {
                        ldsm4t(r, bl + bo);
                        Bl[2*p][0] = r[0]; Bl[2*p][1] = r[1];
                        Bl[2*p+1][0] = r[2]; Bl[2*p+1][1] = r[3];
                    }
                }
            } else {
                const uint32_t bcol2 = (uint32_t)(ks * 16 + ((lane >> 3) & 1) * 8) * 2u;
#pragma unroll
                for (int p = 0; p < 2; p++) {
                    const uint32_t brow = (uint32_t)(wn * 32 + p * 16 + (lane & 7) + ((lane >> 4) << 3));
                    const uint32_t bo = brow * 80u + bcol2;
                    uint32_t r[4];
                    ldsm4(r, bh + bo);
                    Bh[2*p][0] = r[0]; Bh[2*p][1] = r[1];
                    Bh[2*p+1][0] = r[2]; Bh[2*p+1][1] = r[3];
                    if constexpr (HAS_BLO) {
                        ldsm4(r, bl + bo);
                        Bl[2*p][0] = r[0]; Bl[2*p][1] = r[1];
                        Bl[2*p+1][0] = r[2]; Bl[2*p+1][1] = r[3];
                    }
                }
            }
#pragma unroll
            for (int mi = 0; mi < 4; mi++)
#pragma unroll
                for (int ni = 0; ni < 4; ni++) {
                    mma_f16(acc[mi][ni], Ah[mi], Bh[ni]);
                    if constexpr (HAS_BLO) mma_f16(acc[mi][ni], Ah[mi], Bl[ni]);
                    mma_f16(acc[mi][ni], Al[mi], Bh[ni]);
                }
        }
    }
    __syncthreads();
}

// ======================= 1-term fp16 GEMM: C = Ahi * Bhi, B in [k][n], PV_STAGES deep =======================
__device__ __forceinline__ void gemm1_f16(
    const __half* __restrict__ ahi, int lda,
    const __half* __restrict__ bhi, int ldb,
    int nchunks, float (&acc)[4][4][4])
{
    extern __shared__ char smem[];
    const uint32_t sb = smem_u32(smem);
    const int tid = threadIdx.x;
    const int lane = tid & 31, warp = tid >> 5;
    const int wm = warp >> 2, wn = warp & 3;

#pragma unroll
    for (int mi = 0; mi < 4; mi++)
#pragma unroll
        for (int ni = 0; ni < 4; ni++)
#pragma unroll
            for (int k = 0; k < 4; k++) acc[mi][ni][k] = 0.f;

    auto load_chunk = [&](int s, int c) {
        const uint32_t base = sb + (uint32_t)s * STAGE1_B;
        const uint32_t ah = base, bh = base + 10240u;
        int i = tid;
#pragma unroll
        for (int j = 0; j < 2; j++, i += 256) {
            {
                int row = i >> 2, cc = i & 3;
                size_t go = (size_t)row * lda + c * 32 + cc * 8;
                uint32_t so = (uint32_t)row * 80u + (uint32_t)cc * 16u;
                cp16(ah + so, ahi + go);
            }
            {
                int row = i >> 4, cc = i & 15;
                size_t go = (size_t)(c * 32 + row) * ldb + cc * 8;
                uint32_t so = (uint32_t)row * 272u + (uint32_t)cc * 16u;
                cp16(bh + so, bhi + go);
            }
        }
        cp_commit();
    };

#pragma unroll
    for (int s = 0; s < PV_STAGES - 1; s++)
        if (s < nchunks) load_chunk(s, s);

    for (int c = 0; c < nchunks; ++c) {
        cp_wait_stage<PV_STAGES>();
        __syncthreads();
        const int cnext = c + PV_STAGES - 1;
        if (cnext < nchunks) {
            int s = cnext; while (s >= PV_STAGES) s -= PV_STAGES;
            load_chunk(s, cnext);
        } else {
            cp_commit();
        }

        int s = c; while (s >= PV_STAGES) s -= PV_STAGES;
        const uint32_t base = sb + (uint32_t)s * STAGE1_B;
        const uint32_t ah = base, bh = base + 10240u;

#pragma unroll
        for (int ks = 0; ks < 2; ++ks) {
            uint32_t Ah[4][4], Bh[4][2];
            const uint32_t ao = (uint32_t)(wm * 64 + (lane & 15)) * 80u
                              + (uint32_t)(ks * 16 + (lane >> 4) * 8) * 2u;
#pragma unroll
            for (int mi = 0; mi < 4; mi++)
                ldsm4(Ah[mi], ah + ao + (uint32_t)(mi * 16) * 80u);
            const uint32_t brow = (uint32_t)(ks * 16 + (lane & 15));
#pragma unroll
            for (int p = 0; p < 2; p++) {
                const uint32_t bo = brow * 272u
                    + (uint32_t)(wn * 32 + p * 16 + (lane >> 4) * 8) * 2u;
                uint32_t r[4];
                ldsm4t(r, bh + bo);
                Bh[2*p][0] = r[0]; Bh[2*p][1] = r[1];
                Bh[2*p+1][0] = r[2]; Bh[2*p+1][1] = r[3];
            }
#pragma unroll
            for (int mi = 0; mi < 4; mi++)
#pragma unroll
                for (int ni = 0; ni < 4; ni++)
                    mma_f16(acc[mi][ni], Ah[mi], Bh[ni]);
        }
    }
    __syncthreads();
}

// ======================= kernel: split fp32 -> fp16 hi/lo (x + Wq + Wk + Wv) =======================
#define XN ((size_t)MTOT * DIM)          // 8388608
#define WN ((size_t)DIM * DIM)           // 1048576
__global__ __launch_bounds__(256) void split_all(const float* __restrict__ x,
                                                 const float* __restrict__ wq,
                                                 const float* __restrict__ wk,
                                                 const float* __restrict__ wv) {
    size_t i = ((size_t)blockIdx.x * 256 + threadIdx.x) * 4;
    const float* src;
    __half *hi, *lo;
    size_t off;
    if (i < XN) { src = x; off = i; hi = g_xhi; lo = g_xlo; }
    else {
        size_t j = i - XN;
        int w = (int)(j / WN);
        off = j - (size_t)w * WN;
        src = (w == 0) ? wq : (w == 1) ? wk : wv;
        hi = g_whi[w]; lo = g_wlo[w];
    }
    float4 v = *reinterpret_cast<const float4*>(src + off);
    float f[4] = {v.x, v.y, v.z, v.w};
    uint32_t hp[2], lp[2];
#pragma unroll
    for (int j = 0; j < 2; j++) {
        __half h0 = __float2half_rn(f[2*j]),   h1 = __float2half_rn(f[2*j+1]);
        __half l0 = __float2half_rn(f[2*j]   - __half2float(h0));
        __half l1 = __float2half_rn(f[2*j+1] - __half2float(h1));
        hp[j] = (uint32_t)__half_as_ushort(h0) | ((uint32_t)__half_as_ushort(h1) << 16);
        lp[j] = (uint32_t)__half_as_ushort(l0) | ((uint32_t)__half_as_ushort(l1) << 16);
    }
    *reinterpret_cast<uint2*>(hi + off) = make_uint2(hp[0], hp[1]);
    *reinterpret_cast<uint2*>(lo + off) = make_uint2(lp[0], lp[1]);
}

// ======================= kernel: QKV projection (128x128 tile, 256 threads, 3-stage) =======================
// Q,K: 3-term (accurate). V: 2-term (drops W-lo; error linear in output).
__global__ __launch_bounds__(256) void qkv_gemm() {
    const int z = blockIdx.z, m0 = blockIdx.y * 128, n0 = blockIdx.x * 128;
    float acc[4][4][4];
    if (z == 2)
        gemm_f16s<false, true, 3>(g_xhi + (size_t)m0 * DIM, g_xlo + (size_t)m0 * DIM, DIM,
                                  g_whi[2] + n0, nullptr, DIM, DIM / 32, acc);
    else
        gemm_f16s<true, true, 3>(g_xhi + (size_t)m0 * DIM, g_xlo + (size_t)m0 * DIM, DIM,
                                 g_whi[z] + n0, g_wlo[z] + n0, DIM, DIM / 32, acc);
    const int lane = threadIdx.x & 31, warp = threadIdx.x >> 5;
    const int g = lane >> 2, t = lane & 3, wm = warp >> 2, wn = warp & 3;
#pragma unroll
    for (int mi = 0; mi < 4; mi++) {
        const int r0 = m0 + wm * 64 + mi * 16 + g;
#pragma unroll
        for (int ni = 0; ni < 4; ni++) {
            const int cc = n0 + wn * 32 + ni * 8 + 2 * t;
            if (z == 0) {
                st_split2_f16(g_qhi, g_qlo, (size_t)r0 * DIM + cc,       acc[mi][ni][0], acc[mi][ni][1]);
                st_split2_f16(g_qhi, g_qlo, (size_t)(r0 + 8) * DIM + cc, acc[mi][ni][2], acc[mi][ni][3]);
            } else {
                __half* dst = (z == 1) ? g_khi : g_vh;
                __half h0 = __float2half_rn(acc[mi][ni][0]);
                __half h1 = __float2half_rn(acc[mi][ni][1]);
                __half h2 = __float2half_rn(acc[mi][ni][2]);
                __half h3 = __float2half_rn(acc[mi][ni][3]);
                *reinterpret_cast<uint32_t*>(dst + (size_t)r0 * DIM + cc) =
                    (uint32_t)__half_as_ushort(h0) | ((uint32_t)__half_as_ushort(h1) << 16);
                *reinterpret_cast<uint32_t*>(dst + (size_t)(r0 + 8) * DIM + cc) =
                    (uint32_t)__half_as_ushort(h2) | ((uint32_t)__half_as_ushort(h3) << 16);
            }
        }
    }
}

// ======================= kernel: fused scores = exp(QK^T*scale) (causal, 2-term, 3-stage NK) =======================
__global__ __launch_bounds__(256) void scores_gemm() {
    if (blockIdx.x > blockIdx.y) return;     // fully-masked tile, exits immediately
    extern __shared__ char smem[];
    const int b = blockIdx.z, q0 = blockIdx.y * 128, k0 = blockIdx.x * 128;
    const size_t boff = (size_t)b * SEQ * DIM;
    float acc[4][4][4];
    gemm_f16s<false, false, 3>(g_qhi + boff + (size_t)q0 * DIM, g_qlo + boff + (size_t)q0 * DIM, DIM,
                               g_khi + boff + (size_t)k0 * DIM, nullptr, DIM,
                               DIM / 32, acc);
    const bool diag = (blockIdx.x == blockIdx.y);
    __half* ph = g_phi + (size_t)b * SEQ * SEQ;
    const int lane = threadIdx.x & 31, warp = threadIdx.x >> 5;
    const int g = lane >> 2, t = lane & 3, wm = warp >> 2, wn = warp & 3;
    const float scale = 0.03125f;

    float* red = reinterpret_cast<float*>(smem);
    float rs0[4], rs1[4];
#pragma unroll
    for (int mi = 0; mi < 4; mi++) { rs0[mi] = 0.f; rs1[mi] = 0.f; }

#pragma unroll
    for (int mi = 0; mi < 4; mi++) {
        const int r0 = q0 + wm * 64 + mi * 16 + g;
#pragma unroll
        for (int ni = 0; ni < 4; ni++) {
            const int cc = k0 + wn * 32 + ni * 8 + 2 * t;
            float e0 = __expf(acc[mi][ni][0] * scale);
            float e1 = __expf(acc[mi][ni][1] * scale);
            float e2 = __expf(acc[mi][ni][2] * scale);
            float e3 = __expf(acc[mi][ni][3] * scale);
            if (diag) {
                if (cc     > r0)     e0 = 0.f;
                if (cc + 1 > r0)     e1 = 0.f;
                if (cc     > r0 + 8) e2 = 0.f;
                if (cc + 1 > r0 + 8) e3 = 0.f;
            }
            __half p0 = __float2half_rn(e0), p1 = __float2half_rn(e1);
            __half p2 = __float2half_rn(e2), p3 = __float2half_rn(e3);
            *reinterpret_cast<uint32_t*>(ph + (size_t)r0 * SEQ + cc) =
                (uint32_t)__half_as_ushort(p0) | ((uint32_t)__half_as_ushort(p1) << 16);
            *reinterpret_cast<uint32_t*>(ph + (size_t)(r0 + 8) * SEQ + cc) =
                (uint32_t)__half_as_ushort(p2) | ((uint32_t)__half_as_ushort(p3) << 16);
            rs0[mi] += e0 + e1;
            rs1[mi] += e2 + e3;
        }
    }
#pragma unroll
    for (int mi = 0; mi < 4; mi++) {
        float s0 = rs0[mi], s1 = rs1[mi];
        s0 += __shfl_xor_sync(0xFFFFFFFFu, s0, 1);
        s0 += __shfl_xor_sync(0xFFFFFFFFu, s0, 2);
        s1 += __shfl_xor_sync(0xFFFFFFFFu, s1, 1);
        s1 += __shfl_xor_sync(0xFFFFFFFFu, s1, 2);
        if (t == 0) {
            const int lr = wm * 64 + mi * 16 + g;
            red[wn * 128 + lr]     = s0;
            red[wn * 128 + lr + 8] = s1;
        }
    }
    __syncthreads();
    if (threadIdx.x < 128) {
        float tot = red[threadIdx.x] + red[128 + threadIdx.x]
                  + red[256 + threadIdx.x] + red[384 + threadIdx.x];
        g_partial[b][blockIdx.x][q0 + threadIdx.x] = tot;
    }
}

// ======================= kernel: O = (P @ V) * rsuminv (fused rowsum, heavy-first order) =======================
__global__ __launch_bounds__(256) void pv_gemm(float* __restrict__ outp) {
    extern __shared__ char smem[];
    const int b = blockIdx.z, n0 = blockIdx.x * 128;
    const int qy = (int)gridDim.y - 1 - (int)blockIdx.y;   // heavy q-tiles launch first
    const int q0 = qy * 128;

    float* rsinv = reinterpret_cast<float*>(smem + PV_STAGES * STAGE1_B);
    if (threadIdx.x < 128) {
        const int q = q0 + threadIdx.x;
        const int nt = (q0 >> 7) + 1;
        float s = 0.f;
        for (int j = 0; j < nt; j++) s += g_partial[b][j][q];
        rsinv[threadIdx.x] = 1.f / s;
    }

    float acc[4][4][4];
    gemm1_f16(g_phi + (size_t)b * SEQ * SEQ + (size_t)q0 * SEQ, SEQ,
              g_vh + (size_t)b * SEQ * DIM + n0, DIM,
              (q0 + 128) / 32, acc);   // ends with __syncthreads -> rsinv visible
    float* out = outp + (size_t)b * SEQ * DIM;
    const int lane = threadIdx.x & 31, warp = threadIdx.x >> 5;
    const int g = lane >> 2, t = lane & 3, wm = warp >> 2, wn = warp & 3;
#pragma unroll
    for (int mi = 0; mi < 4; mi++) {
        const int lr = wm * 64 + mi * 16 + g;
        const int r0 = q0 + lr;
        const float i0 = rsinv[lr], i1 = rsinv[lr + 8];
#pragma unroll
        for (int ni = 0; ni < 4; ni++) {
            const int cc = n0 + wn * 32 + ni * 8 + 2 * t;
            *reinterpret_cast<float2*>(out + (size_t)r0 * DIM + cc) =
                make_float2(acc[mi][ni][0] * i0, acc[mi][ni][1] * i0);
            *reinterpret_cast<float2*>(out + (size_t)(r0 + 8) * DIM + cc) =
                make_float2(acc[mi][ni][2] * i1, acc[mi][ni][3] * i1);
        }
    }
}

// ======================= launch =======================
extern "C" void kernel_launch(void* const* d_in, const int* in_sizes, int n_in,
                              void* d_out, int out_size) {
    const float* x  = (const float*)d_in[0];
    const float* Wq = (const float*)d_in[1];
    const float* Wk = (const float*)d_in[2];
    const float* Wv = (const float*)d_in[3];
    float* out = (float*)d_out;

    cudaFuncSetAttribute(qkv_gemm,    cudaFuncAttributeMaxDynamicSharedMemorySize, SMEM3Q_BYTES);
    cudaFuncSetAttribute(scores_gemm, cudaFuncAttributeMaxDynamicSharedMemorySize, SMEMS_BYTES);
    cudaFuncSetAttribute(pv_gemm,     cudaFuncAttributeMaxDynamicSharedMemorySize, SMEM1_BYTES);

    const size_t total = XN + 3 * WN;
    split_all<<<(unsigned)(total / 1024), 256>>>(x, Wq, Wk, Wv);

    qkv_gemm<<<dim3(DIM / 128, MTOT / 128, 3), 256, SMEM3Q_BYTES>>>();
    scores_gemm<<<dim3(SEQ / 128, SEQ / 128, BATCH), 256, SMEMS_BYTES>>>();
    pv_gemm<<<dim3(DIM / 128, SEQ / 128, BATCH), 256, SMEM1_BYTES>>>(out);
}

// round 14
// speedup vs baseline: 1.3668x; 1.1754x over previous
#include <cuda_runtime.h>
#include <cuda_fp16.h>
#include <math.h>
#include <stdint.h>

#define BATCH 4
#define SEQ   2048
#define DIM   1024
#define MTOT  (BATCH * SEQ)   // 8192

// ======================= device scratch (no runtime alloc) =======================
__device__ __align__(128) __half g_xhi[(size_t)MTOT * DIM];
__device__ __align__(128) __half g_xlo[(size_t)MTOT * DIM];
__device__ __align__(128) __half g_whi[3][(size_t)DIM * DIM];   // [din][dout]
__device__ __align__(128) __half g_wlo[(size_t)DIM * DIM];      // only K's W needs lo
__device__ __align__(128) __half g_qhi[(size_t)MTOT * DIM];     // Q fp16 (hi only)
__device__ __align__(128) __half g_khi[(size_t)MTOT * DIM];     // K fp16 (hi only)
__device__ __align__(128) __half g_vh[(size_t)MTOT * DIM];      // V fp16 (hi only)
__device__ __align__(128) __half g_phi[(size_t)BATCH * SEQ * SEQ]; // unnorm probs
__device__ __align__(128) float  g_partial[BATCH][SEQ / 128][SEQ]; // rowsum partials

// ======================= PTX helpers (arch-agnostic, sm_80-era) =======================
__device__ __forceinline__ uint32_t smem_u32(const void* p) {
    uint32_t a;
    asm("{ .reg .u64 t; cvta.to.shared.u64 t, %1; cvt.u32.u64 %0, t; }" : "=r"(a) : "l"(p));
    return a;
}
__device__ __forceinline__ void cp16(uint32_t dst, const void* src) {
    asm volatile("cp.async.cg.shared.global [%0], [%1], 16;" :: "r"(dst), "l"(src));
}
__device__ __forceinline__ void cp_commit() { asm volatile("cp.async.commit_group;"); }
template<int N>
__device__ __forceinline__ void cp_wait() { asm volatile("cp.async.wait_group %0;" :: "n"(N)); }
template<int NSTAGES>
__device__ __forceinline__ void cp_wait_stage() {
    if constexpr (NSTAGES == 2)      cp_wait<0>();
    else if constexpr (NSTAGES == 3) cp_wait<1>();
    else                             cp_wait<2>();
}

__device__ __forceinline__ void ldsm4(uint32_t* r, uint32_t a) {
    asm volatile("ldmatrix.sync.aligned.m8n8.x4.shared.b16 {%0,%1,%2,%3}, [%4];"
                 : "=r"(r[0]), "=r"(r[1]), "=r"(r[2]), "=r"(r[3]) : "r"(a));
}
__device__ __forceinline__ void ldsm4t(uint32_t* r, uint32_t a) {
    asm volatile("ldmatrix.sync.aligned.m8n8.x4.trans.shared.b16 {%0,%1,%2,%3}, [%4];"
                 : "=r"(r[0]), "=r"(r[1]), "=r"(r[2]), "=r"(r[3]) : "r"(a));
}
__device__ __forceinline__ void mma_f16(float* c, const uint32_t* a, const uint32_t* b) {
    asm volatile(
        "mma.sync.aligned.m16n8k16.row.col.f32.f16.f16.f32 "
        "{%0,%1,%2,%3},{%4,%5,%6,%7},{%8,%9},{%0,%1,%2,%3};"
        : "+f"(c[0]), "+f"(c[1]), "+f"(c[2]), "+f"(c[3])
        : "r"(a[0]), "r"(a[1]), "r"(a[2]), "r"(a[3]), "r"(b[0]), "r"(b[1]));
}

// ======================= smem layouts =======================
// Stage = A(10240 x (1+ALO)) + B(BT x (1+BLO)); BT = 8704 (KN, ldsm.trans) / 10240 (NK, ldsm)
// qkv K (ALO+BLO, KN):  37888/stage, 3 stages = 113664 (2 CTAs/SM, proven)
// qkv Q,V (ALO, KN):    29184/stage (fits same alloc)
// scores (1-term, NK):  20480/stage, 4 stages = 81920 (2 CTAs/SM)
// pv (1-term, KN):      18944/stage, 4 stages + 512 = 76288 (R10 optimum)
#define PV_STAGE_B  18944
#define PV_STAGES   4
#define SMEM_PV     (PV_STAGES * PV_STAGE_B + 512)   // 76288
#define SMEM_QKV    (3 * 37888)                      // 113664
#define SMEM_SC     (4 * 20480)                      // 81920

// ======================= unified split-fp16 GEMM (128x128 tile, 256 thr) =======================
// acc += Ahi*Bhi (+ Ahi*Blo if HAS_BLO) (+ Alo*Bhi if HAS_ALO)
// BKN=true : B stored [k][n] row-major (ldb=n-stride), ldmatrix.trans
// BKN=false: B stored [n][k] row-major (ldb=k-stride), ldmatrix
// One commit_group per loop iteration (empty at tail) keeps wait<k> accounting exact.
template<bool HAS_ALO, bool HAS_BLO, bool BKN, int NSTAGES>
__device__ __forceinline__ void gemm_f16s(
    const __half* __restrict__ ahi, const __half* __restrict__ alo, int lda,
    const __half* __restrict__ bhi, const __half* __restrict__ blo, int ldb,
    int nchunks, float (&acc)[4][4][4])
{
    extern __shared__ char smem[];
    const uint32_t sb = smem_u32(smem);
    const int tid = threadIdx.x;
    const int lane = tid & 31, warp = tid >> 5;
    const int wm = warp >> 2, wn = warp & 3;
    constexpr int BT = BKN ? 8704 : 10240;
    constexpr uint32_t BOFF = HAS_ALO ? 20480u : 10240u;
    constexpr int STAGE = (int)BOFF + (HAS_BLO ? 2 : 1) * BT;

#pragma unroll
    for (int mi = 0; mi < 4; mi++)
#pragma unroll
        for (int ni = 0; ni < 4; ni++)
#pragma unroll
            for (int k = 0; k < 4; k++) acc[mi][ni][k] = 0.f;

    auto load_chunk = [&](int s, int c) {
        const uint32_t base = sb + (uint32_t)s * STAGE;
        const uint32_t ah = base, al = base + 10240u;
        const uint32_t bh = base + BOFF, bl = base + BOFF + (uint32_t)BT;
        int i = tid;
#pragma unroll
        for (int j = 0; j < 2; j++, i += 256) {
            {
                int row = i >> 2, cc = i & 3;
                size_t go = (size_t)row * lda + c * 32 + cc * 8;
                uint32_t so = (uint32_t)row * 80u + (uint32_t)cc * 16u;
                cp16(ah + so, ahi + go);
                if constexpr (HAS_ALO) cp16(al + so, alo + go);
            }
            if (BKN) {
                int row = i >> 4, cc = i & 15;
                size_t go = (size_t)(c * 32 + row) * ldb + cc * 8;
                uint32_t so = (uint32_t)row * 272u + (uint32_t)cc * 16u;
                cp16(bh + so, bhi + go);
                if constexpr (HAS_BLO) cp16(bl + so, blo + go);
            } else {
                int row = i >> 2, cc = i & 3;
                size_t go = (size_t)row * ldb + c * 32 + cc * 8;
                uint32_t so = (uint32_t)row * 80u + (uint32_t)cc * 16u;
                cp16(bh + so, bhi + go);
                if constexpr (HAS_BLO) cp16(bl + so, blo + go);
            }
        }
        cp_commit();
    };

#pragma unroll
    for (int s = 0; s < NSTAGES - 1; s++)
        if (s < nchunks) load_chunk(s, s);

    for (int c = 0; c < nchunks; ++c) {
        cp_wait_stage<NSTAGES>();
        __syncthreads();
        const int cnext = c + NSTAGES - 1;
        if (cnext < nchunks) {
            int s = cnext; while (s >= NSTAGES) s -= NSTAGES;
            load_chunk(s, cnext);
        } else {
            cp_commit();
        }

        int s = c; while (s >= NSTAGES) s -= NSTAGES;
        const uint32_t base = sb + (uint32_t)s * STAGE;
        const uint32_t ah = base, al = base + 10240u;
        const uint32_t bh = base + BOFF, bl = base + BOFF + (uint32_t)BT;

#pragma unroll
        for (int ks = 0; ks < 2; ++ks) {
            uint32_t Ah[4][4], Al[4][4], Bh[4][2], Bl[4][2];
            const uint32_t ao = (uint32_t)(wm * 64 + (lane & 15)) * 80u
                              + (uint32_t)(ks * 16 + (lane >> 4) * 8) * 2u;
#pragma unroll
            for (int mi = 0; mi < 4; mi++) {
                ldsm4(Ah[mi], ah + ao + (uint32_t)(mi * 16) * 80u);
                if constexpr (HAS_ALO) ldsm4(Al[mi], al + ao + (uint32_t)(mi * 16) * 80u);
            }
            if (BKN) {
                const uint32_t brow = (uint32_t)(ks * 16 + (lane & 15));
#pragma unroll
                for (int p = 0; p < 2; p++) {
                    const uint32_t bo = brow * 272u
                        + (uint32_t)(wn * 32 + p * 16 + (lane >> 4) * 8) * 2u;
                    uint32_t r[4];
                    ldsm4t(r, bh + bo);
                    Bh[2*p][0] = r[0]; Bh[2*p][1] = r[1];
                    Bh[2*p+1][0] = r[2]; Bh[2*p+1][1] = r[3];
                    if constexpr (HAS_BLO) {
                        ldsm4t(r, bl + bo);
                        Bl[2*p][0] = r[0]; Bl[2*p][1] = r[1];
                        Bl[2*p+1][0] = r[2]; Bl[2*p+1][1] = r[3];
                    }
                }
            } else {
                const uint32_t bcol2 = (uint32_t)(ks * 16 + ((lane >> 3) & 1) * 8) * 2u;
#pragma unroll
                for (int p = 0; p < 2; p++) {
                    const uint32_t brow = (uint32_t)(wn * 32 + p * 16 + (lane & 7) + ((lane >> 4) << 3));
                    const uint32_t bo = brow * 80u + bcol2;
                    uint32_t r[4];
                    ldsm4(r, bh + bo);
                    Bh[2*p][0] = r[0]; Bh[2*p][1] = r[1];
                    Bh[2*p+1][0] = r[2]; Bh[2*p+1][1] = r[3];
                    if constexpr (HAS_BLO) {
                        ldsm4(r, bl + bo);
                        Bl[2*p][0] = r[0]; Bl[2*p][1] = r[1];
                        Bl[2*p+1][0] = r[2]; Bl[2*p+1][1] = r[3];
                    }
                }
            }
#pragma unroll
            for (int mi = 0; mi < 4; mi++)
#pragma unroll
                for (int ni = 0; ni < 4; ni++) {
                    mma_f16(acc[mi][ni], Ah[mi], Bh[ni]);
                    if constexpr (HAS_BLO) mma_f16(acc[mi][ni], Ah[mi], Bl[ni]);
                    if constexpr (HAS_ALO) mma_f16(acc[mi][ni], Al[mi], Bh[ni]);
                }
        }
    }
    __syncthreads();
}

// ======================= kernel: split fp32 -> fp16 hi/lo =======================
// x -> hi+lo; Wq,Wv -> hi only; Wk -> hi+lo
#define XN ((size_t)MTOT * DIM)          // 8388608
#define WN ((size_t)DIM * DIM)           // 1048576
__global__ __launch_bounds__(256) void split_all(const float* __restrict__ x,
                                                 const float* __restrict__ wq,
                                                 const float* __restrict__ wk,
                                                 const float* __restrict__ wv) {
    size_t i = ((size_t)blockIdx.x * 256 + threadIdx.x) * 4;
    const float* src;
    __half *hi, *lo = nullptr;
    size_t off;
    if (i < XN) { src = x; off = i; hi = g_xhi; lo = g_xlo; }
    else {
        size_t j = i - XN;
        int w = (int)(j / WN);
        off = j - (size_t)w * WN;
        src = (w == 0) ? wq : (w == 1) ? wk : wv;
        hi = g_whi[w];
        if (w == 1) lo = g_wlo;
    }
    float4 v = *reinterpret_cast<const float4*>(src + off);
    float f[4] = {v.x, v.y, v.z, v.w};
    uint32_t hp[2], lp[2];
#pragma unroll
    for (int j = 0; j < 2; j++) {
        __half h0 = __float2half_rn(f[2*j]),   h1 = __float2half_rn(f[2*j+1]);
        __half l0 = __float2half_rn(f[2*j]   - __half2float(h0));
        __half l1 = __float2half_rn(f[2*j+1] - __half2float(h1));
        hp[j] = (uint32_t)__half_as_ushort(h0) | ((uint32_t)__half_as_ushort(h1) << 16);
        lp[j] = (uint32_t)__half_as_ushort(l0) | ((uint32_t)__half_as_ushort(l1) << 16);
    }
    *reinterpret_cast<uint2*>(hi + off) = make_uint2(hp[0], hp[1]);
    if (lo) *reinterpret_cast<uint2*>(lo + off) = make_uint2(lp[0], lp[1]);
}

// ======================= kernel: QKV projection (128x128 tile, 256 threads, 3-stage) =======================
// Q: 2-term (Xhi+Xlo)*Whi. K: 3-term (+Xhi*Wlo). V: 2-term. All stored fp16-hi.
__global__ __launch_bounds__(256) void qkv_gemm() {
    const int z = blockIdx.z, m0 = blockIdx.y * 128, n0 = blockIdx.x * 128;
    float acc[4][4][4];
    if (z == 1)
        gemm_f16s<true, true, true, 3>(g_xhi + (size_t)m0 * DIM, g_xlo + (size_t)m0 * DIM, DIM,
                                       g_whi[1] + n0, g_wlo + n0, DIM, DIM / 32, acc);
    else
        gemm_f16s<true, false, true, 3>(g_xhi + (size_t)m0 * DIM, g_xlo + (size_t)m0 * DIM, DIM,
                                        g_whi[z] + n0, nullptr, DIM, DIM / 32, acc);
    const int lane = threadIdx.x & 31, warp = threadIdx.x >> 5;
    const int g = lane >> 2, t = lane & 3, wm = warp >> 2, wn = warp & 3;
    __half* dst = (z == 0) ? g_qhi : (z == 1) ? g_khi : g_vh;
#pragma unroll
    for (int mi = 0; mi < 4; mi++) {
        const int r0 = m0 + wm * 64 + mi * 16 + g;
#pragma unroll
        for (int ni = 0; ni < 4; ni++) {
            const int cc = n0 + wn * 32 + ni * 8 + 2 * t;
            __half h0 = __float2half_rn(acc[mi][ni][0]);
            __half h1 = __float2half_rn(acc[mi][ni][1]);
            __half h2 = __float2half_rn(acc[mi][ni][2]);
            __half h3 = __float2half_rn(acc[mi][ni][3]);
            *reinterpret_cast<uint32_t*>(dst + (size_t)r0 * DIM + cc) =
                (uint32_t)__half_as_ushort(h0) | ((uint32_t)__half_as_ushort(h1) << 16);
            *reinterpret_cast<uint32_t*>(dst + (size_t)(r0 + 8) * DIM + cc) =
                (uint32_t)__half_as_ushort(h2) | ((uint32_t)__half_as_ushort(h3) << 16);
        }
    }
}

// ======================= kernel: fused scores = exp(Qhi·Khi^T*scale) (causal, 1-term, 4-stage NK) =======================
__global__ __launch_bounds__(256) void scores_gemm() {
    if (blockIdx.x > blockIdx.y) return;     // fully-masked tile, exits immediately
    extern __shared__ char smem[];
    const int b = blockIdx.z, q0 = blockIdx.y * 128, k0 = blockIdx.x * 128;
    const size_t boff = (size_t)b * SEQ * DIM;
    float acc[4][4][4];
    gemm_f16s<false, false, false, 4>(g_qhi + boff + (size_t)q0 * DIM, nullptr, DIM,
                                      g_khi + boff + (size_t)k0 * DIM, nullptr, DIM,
                                      DIM / 32, acc);
    const bool diag = (blockIdx.x == blockIdx.y);
    __half* ph = g_phi + (size_t)b * SEQ * SEQ;
    const int lane = threadIdx.x & 31, warp = threadIdx.x >> 5;
    const int g = lane >> 2, t = lane & 3, wm = warp >> 2, wn = warp & 3;
    const float scale = 0.03125f;

    float* red = reinterpret_cast<float*>(smem);
    float rs0[4], rs1[4];
#pragma unroll
    for (int mi = 0; mi < 4; mi++) { rs0[mi] = 0.f; rs1[mi] = 0.f; }

#pragma unroll
    for (int mi = 0; mi < 4; mi++) {
        const int r0 = q0 + wm * 64 + mi * 16 + g;
#pragma unroll
        for (int ni = 0; ni < 4; ni++) {
            const int cc = k0 + wn * 32 + ni * 8 + 2 * t;
            float e0 = __expf(acc[mi][ni][0] * scale);
            float e1 = __expf(acc[mi][ni][1] * scale);
            float e2 = __expf(acc[mi][ni][2] * scale);
            float e3 = __expf(acc[mi][ni][3] * scale);
            if (diag) {
                if (cc     > r0)     e0 = 0.f;
                if (cc + 1 > r0)     e1 = 0.f;
                if (cc     > r0 + 8) e2 = 0.f;
                if (cc + 1 > r0 + 8) e3 = 0.f;
            }
            __half p0 = __float2half_rn(e0), p1 = __float2half_rn(e1);
            __half p2 = __float2half_rn(e2), p3 = __float2half_rn(e3);
            *reinterpret_cast<uint32_t*>(ph + (size_t)r0 * SEQ + cc) =
                (uint32_t)__half_as_ushort(p0) | ((uint32_t)__half_as_ushort(p1) << 16);
            *reinterpret_cast<uint32_t*>(ph + (size_t)(r0 + 8) * SEQ + cc) =
                (uint32_t)__half_as_ushort(p2) | ((uint32_t)__half_as_ushort(p3) << 16);
            rs0[mi] += e0 + e1;
            rs1[mi] += e2 + e3;
        }
    }
#pragma unroll
    for (int mi = 0; mi < 4; mi++) {
        float s0 = rs0[mi], s1 = rs1[mi];
        s0 += __shfl_xor_sync(0xFFFFFFFFu, s0, 1);
        s0 += __shfl_xor_sync(0xFFFFFFFFu, s0, 2);
        s1 += __shfl_xor_sync(0xFFFFFFFFu, s1, 1);
        s1 += __shfl_xor_sync(0xFFFFFFFFu, s1, 2);
        if (t == 0) {
            const int lr = wm * 64 + mi * 16 + g;
            red[wn * 128 + lr]     = s0;
            red[wn * 128 + lr + 8] = s1;
        }
    }
    __syncthreads();
    if (threadIdx.x < 128) {
        float tot = red[threadIdx.x] + red[128 + threadIdx.x]
                  + red[256 + threadIdx.x] + red[384 + threadIdx.x];
        g_partial[b][blockIdx.x][q0 + threadIdx.x] = tot;
    }
}

// ======================= kernel: O = (P @ V) * rsuminv (fused rowsum, heavy-first order) =======================
__global__ __launch_bounds__(256) void pv_gemm(float* __restrict__ outp) {
    extern __shared__ char smem[];
    const int b = blockIdx.z, n0 = blockIdx.x * 128;
    const int qy = (int)gridDim.y - 1 - (int)blockIdx.y;   // heavy q-tiles launch first
    const int q0 = qy * 128;

    float* rsinv = reinterpret_cast<float*>(smem + PV_STAGES * PV_STAGE_B);
    if (threadIdx.x < 128) {
        const int q = q0 + threadIdx.x;
        const int nt = (q0 >> 7) + 1;
        float s = 0.f;
        for (int j = 0; j < nt; j++) s += g_partial[b][j][q];
        rsinv[threadIdx.x] = 1.f / s;
    }

    float acc[4][4][4];
    gemm_f16s<false, false, true, PV_STAGES>(
        g_phi + (size_t)b * SEQ * SEQ + (size_t)q0 * SEQ, nullptr, SEQ,
        g_vh + (size_t)b * SEQ * DIM + n0, nullptr, DIM,
        (q0 + 128) / 32, acc);   // ends with __syncthreads -> rsinv visible
    float* out = outp + (size_t)b * SEQ * DIM;
    const int lane = threadIdx.x & 31, warp = threadIdx.x >> 5;
    const int g = lane >> 2, t = lane & 3, wm = warp >> 2, wn = warp & 3;
#pragma unroll
    for (int mi = 0; mi < 4; mi++) {
        const int lr = wm * 64 + mi * 16 + g;
        const int r0 = q0 + lr;
        const float i0 = rsinv[lr], i1 = rsinv[lr + 8];
#pragma unroll
        for (int ni = 0; ni < 4; ni++) {
            const int cc = n0 + wn * 32 + ni * 8 + 2 * t;
            *reinterpret_cast<float2*>(out + (size_t)r0 * DIM + cc) =
                make_float2(acc[mi][ni][0] * i0, acc[mi][ni][1] * i0);
            *reinterpret_cast<float2*>(out + (size_t)(r0 + 8) * DIM + cc) =
                make_float2(acc[mi][ni][2] * i1, acc[mi][ni][3] * i1);
        }
    }
}

// ======================= launch =======================
extern "C" void kernel_launch(void* const* d_in, const int* in_sizes, int n_in,
                              void* d_out, int out_size) {
    const float* x  = (const float*)d_in[0];
    const float* Wq = (const float*)d_in[1];
    const float* Wk = (const float*)d_in[2];
    const float* Wv = (const float*)d_in[3];
    float* out = (float*)d_out;

    cudaFuncSetAttribute(qkv_gemm,    cudaFuncAttributeMaxDynamicSharedMemorySize, SMEM_QKV);
    cudaFuncSetAttribute(scores_gemm, cudaFuncAttributeMaxDynamicSharedMemorySize, SMEM_SC);
    cudaFuncSetAttribute(pv_gemm,     cudaFuncAttributeMaxDynamicSharedMemorySize, SMEM_PV);

    const size_t total = XN + 3 * WN;
    split_all<<<(unsigned)(total / 1024), 256>>>(x, Wq, Wk, Wv);

    qkv_gemm<<<dim3(DIM / 128, MTOT / 128, 3), 256, SMEM_QKV>>>();
    scores_gemm<<<dim3(SEQ / 128, SEQ / 128, BATCH), 256, SMEM_SC>>>();
    pv_gemm<<<dim3(DIM / 128, SEQ / 128, BATCH), 256, SMEM_PV>>>(out);
}

// round 15
// speedup vs baseline: 1.9517x; 1.4279x over previous
#include <cuda_runtime.h>
#include <cuda_fp16.h>
#include <math.h>
#include <stdint.h>

#define BATCH 4
#define SEQ   2048
#define DIM   1024
#define MTOT  (BATCH * SEQ)   // 8192

// ======================= device scratch (no runtime alloc) =======================
__device__ __align__(128) __half g_xh[(size_t)MTOT * DIM];      // X fp16
__device__ __align__(128) __half g_wh[3][(size_t)DIM * DIM];    // W fp16 [din][dout]
__device__ __align__(128) __half g_qh[(size_t)MTOT * DIM];      // Q fp16
__device__ __align__(128) __half g_kh[(size_t)MTOT * DIM];      // K fp16
__device__ __align__(128) __half g_vh[(size_t)MTOT * DIM];      // V fp16
__device__ __align__(128) __half g_ph[(size_t)BATCH * SEQ * SEQ]; // unnorm probs
__device__ __align__(128) float  g_partial[BATCH][SEQ / 128][SEQ]; // rowsum partials

// ======================= PTX helpers (arch-agnostic, sm_80-era) =======================
__device__ __forceinline__ uint32_t smem_u32(const void* p) {
    uint32_t a;
    asm("{ .reg .u64 t; cvta.to.shared.u64 t, %1; cvt.u32.u64 %0, t; }" : "=r"(a) : "l"(p));
    return a;
}
__device__ __forceinline__ void cp16(uint32_t dst, const void* src) {
    asm volatile("cp.async.cg.shared.global [%0], [%1], 16;" :: "r"(dst), "l"(src));
}
__device__ __forceinline__ void cp_commit() { asm volatile("cp.async.commit_group;"); }
template<int N>
__device__ __forceinline__ void cp_wait() { asm volatile("cp.async.wait_group %0;" :: "n"(N)); }
template<int NSTAGES>
__device__ __forceinline__ void cp_wait_stage() {
    if constexpr (NSTAGES == 2)      cp_wait<0>();
    else if constexpr (NSTAGES == 3) cp_wait<1>();
    else                             cp_wait<2>();
}

__device__ __forceinline__ void ldsm4(uint32_t* r, uint32_t a) {
    asm volatile("ldmatrix.sync.aligned.m8n8.x4.shared.b16 {%0,%1,%2,%3}, [%4];"
                 : "=r"(r[0]), "=r"(r[1]), "=r"(r[2]), "=r"(r[3]) : "r"(a));
}
__device__ __forceinline__ void ldsm4t(uint32_t* r, uint32_t a) {
    asm volatile("ldmatrix.sync.aligned.m8n8.x4.trans.shared.b16 {%0,%1,%2,%3}, [%4];"
                 : "=r"(r[0]), "=r"(r[1]), "=r"(r[2]), "=r"(r[3]) : "r"(a));
}
__device__ __forceinline__ void mma_f16(float* c, const uint32_t* a, const uint32_t* b) {
    asm volatile(
        "mma.sync.aligned.m16n8k16.row.col.f32.f16.f16.f32 "
        "{%0,%1,%2,%3},{%4,%5,%6,%7},{%8,%9},{%0,%1,%2,%3};"
        : "+f"(c[0]), "+f"(c[1]), "+f"(c[2]), "+f"(c[3])
        : "r"(a[0]), "r"(a[1]), "r"(a[2]), "r"(a[3]), "r"(b[0]), "r"(b[1]));
}

// ======================= smem layouts =======================
// 1-term stage = A(10240) + B(BT); BT = 8704 (KN, ldsm.trans) / 10240 (NK, ldsm)
// qkv (KN):    18944/stage, 4 stages = 75776  (2 CTAs/SM, pv-proven)
// scores (NK): 20480/stage, 4 stages = 81920  (2 CTAs/SM)
// pv (KN):     18944/stage, 4 stages + 512 = 76288 (R10 optimum)
#define PV_STAGE_B  18944
#define PV_STAGES   4
#define SMEM_PV     (PV_STAGES * PV_STAGE_B + 512)   // 76288
#define SMEM_QKV    (4 * 18944)                      // 75776
#define SMEM_SC     (4 * 20480)                      // 81920

// ======================= unified 1-term fp16 GEMM (128x128 tile, 256 thr) =======================
// acc += A*B, fp32 accumulate.
// BKN=true : B stored [k][n] row-major (ldb=n-stride), ldmatrix.trans
// BKN=false: B stored [n][k] row-major (ldb=k-stride), ldmatrix
// One commit_group per loop iteration (empty at tail) keeps wait<k> accounting exact.
template<bool BKN, int NSTAGES>
__device__ __forceinline__ void gemm_f16(
    const __half* __restrict__ a, int lda,
    const __half* __restrict__ b, int ldb,
    int nchunks, float (&acc)[4][4][4])
{
    extern __shared__ char smem[];
    const uint32_t sb = smem_u32(smem);
    const int tid = threadIdx.x;
    const int lane = tid & 31, warp = tid >> 5;
    const int wm = warp >> 2, wn = warp & 3;
    constexpr int BT = BKN ? 8704 : 10240;
    constexpr int STAGE = 10240 + BT;

#pragma unroll
    for (int mi = 0; mi < 4; mi++)
#pragma unroll
        for (int ni = 0; ni < 4; ni++)
#pragma unroll
            for (int k = 0; k < 4; k++) acc[mi][ni][k] = 0.f;

    auto load_chunk = [&](int s, int c) {
        const uint32_t base = sb + (uint32_t)s * STAGE;
        const uint32_t ah = base, bh = base + 10240u;
        int i = tid;
#pragma unroll
        for (int j = 0; j < 2; j++, i += 256) {
            {
                int row = i >> 2, cc = i & 3;
                size_t go = (size_t)row * lda + c * 32 + cc * 8;
                uint32_t so = (uint32_t)row * 80u + (uint32_t)cc * 16u;
                cp16(ah + so, a + go);
            }
            if (BKN) {
                int row = i >> 4, cc = i & 15;
                size_t go = (size_t)(c * 32 + row) * ldb + cc * 8;
                uint32_t so = (uint32_t)row * 272u + (uint32_t)cc * 16u;
                cp16(bh + so, b + go);
            } else {
                int row = i >> 2, cc = i & 3;
                size_t go = (size_t)row * ldb + c * 32 + cc * 8;
                uint32_t so = (uint32_t)row * 80u + (uint32_t)cc * 16u;
                cp16(bh + so, b + go);
            }
        }
        cp_commit();
    };

#pragma unroll
    for (int s = 0; s < NSTAGES - 1; s++)
        if (s < nchunks) load_chunk(s, s);

    for (int c = 0; c < nchunks; ++c) {
        cp_wait_stage<NSTAGES>();
        __syncthreads();
        const int cnext = c + NSTAGES - 1;
        if (cnext < nchunks) {
            int s = cnext; while (s >= NSTAGES) s -= NSTAGES;
            load_chunk(s, cnext);
        } else {
            cp_commit();
        }

        int s = c; while (s >= NSTAGES) s -= NSTAGES;
        const uint32_t base = sb + (uint32_t)s * STAGE;
        const uint32_t ah = base, bh = base + 10240u;

#pragma unroll
        for (int ks = 0; ks < 2; ++ks) {
            uint32_t Ah[4][4], Bh[4][2];
            const uint32_t ao = (uint32_t)(wm * 64 + (lane & 15)) * 80u
                              + (uint32_t)(ks * 16 + (lane >> 4) * 8) * 2u;
#pragma unroll
            for (int mi = 0; mi < 4; mi++)
                ldsm4(Ah[mi], ah + ao + (uint32_t)(mi * 16) * 80u);
            if (BKN) {
                const uint32_t brow = (uint32_t)(ks * 16 + (lane & 15));
#pragma unroll
                for (int p = 0; p < 2; p++) {
                    const uint32_t bo = brow * 272u
                        + (uint32_t)(wn * 32 + p * 16 + (lane >> 4) * 8) * 2u;
                    uint32_t r[4];
                    ldsm4t(r, bh + bo);
                    Bh[2*p][0] = r[0]; Bh[2*p][1] = r[1];
                    Bh[2*p+1][0] = r[2]; Bh[2*p+1][1] = r[3];
                }
            } else {
                const uint32_t bcol2 = (uint32_t)(ks * 16 + ((lane >> 3) & 1) * 8) * 2u;
#pragma unroll
                for (int p = 0; p < 2; p++) {
                    const uint32_t brow = (uint32_t)(wn * 32 + p * 16 + (lane & 7) + ((lane >> 4) << 3));
                    const uint32_t bo = brow * 80u + bcol2;
                    uint32_t r[4];
                    ldsm4(r, bh + bo);
                    Bh[2*p][0] = r[0]; Bh[2*p][1] = r[1];
                    Bh[2*p+1][0] = r[2]; Bh[2*p+1][1] = r[3];
                }
            }
#pragma unroll
            for (int mi = 0; mi < 4; mi++)
#pragma unroll
                for (int ni = 0; ni < 4; ni++)
                    mma_f16(acc[mi][ni], Ah[mi], Bh[ni]);
        }
    }
    __syncthreads();
}

// ======================= kernel: convert fp32 -> fp16 (x + Wq + Wk + Wv) =======================
#define XN ((size_t)MTOT * DIM)          // 8388608
#define WN ((size_t)DIM * DIM)           // 1048576
__global__ __launch_bounds__(256) void split_all(const float* __restrict__ x,
                                                 const float* __restrict__ wq,
                                                 const float* __restrict__ wk,
                                                 const float* __restrict__ wv) {
    size_t i = ((size_t)blockIdx.x * 256 + threadIdx.x) * 4;
    const float* src;
    __half* hi;
    size_t off;
    if (i < XN) { src = x; off = i; hi = g_xh; }
    else {
        size_t j = i - XN;
        int w = (int)(j / WN);
        off = j - (size_t)w * WN;
        src = (w == 0) ? wq : (w == 1) ? wk : wv;
        hi = g_wh[w];
    }
    float4 v = *reinterpret_cast<const float4*>(src + off);
    __half h0 = __float2half_rn(v.x), h1 = __float2half_rn(v.y);
    __half h2 = __float2half_rn(v.z), h3 = __float2half_rn(v.w);
    uint32_t p0 = (uint32_t)__half_as_ushort(h0) | ((uint32_t)__half_as_ushort(h1) << 16);
    uint32_t p1 = (uint32_t)__half_as_ushort(h2) | ((uint32_t)__half_as_ushort(h3) << 16);
    *reinterpret_cast<uint2*>(hi + off) = make_uint2(p0, p1);
}

// ======================= kernel: QKV projection (1-term, 128x128 tile, 4-stage KN) =======================
__global__ __launch_bounds__(256) void qkv_gemm() {
    const int z = blockIdx.z, m0 = blockIdx.y * 128, n0 = blockIdx.x * 128;
    float acc[4][4][4];
    gemm_f16<true, 4>(g_xh + (size_t)m0 * DIM, DIM, g_wh[z] + n0, DIM, DIM / 32, acc);
    const int lane = threadIdx.x & 31, warp = threadIdx.x >> 5;
    const int g = lane >> 2, t = lane & 3, wm = warp >> 2, wn = warp & 3;
    __half* dst = (z == 0) ? g_qh : (z == 1) ? g_kh : g_vh;
#pragma unroll
    for (int mi = 0; mi < 4; mi++) {
        const int r0 = m0 + wm * 64 + mi * 16 + g;
#pragma unroll
        for (int ni = 0; ni < 4; ni++) {
            const int cc = n0 + wn * 32 + ni * 8 + 2 * t;
            __half h0 = __float2half_rn(acc[mi][ni][0]);
            __half h1 = __float2half_rn(acc[mi][ni][1]);
            __half h2 = __float2half_rn(acc[mi][ni][2]);
            __half h3 = __float2half_rn(acc[mi][ni][3]);
            *reinterpret_cast<uint32_t*>(dst + (size_t)r0 * DIM + cc) =
                (uint32_t)__half_as_ushort(h0) | ((uint32_t)__half_as_ushort(h1) << 16);
            *reinterpret_cast<uint32_t*>(dst + (size_t)(r0 + 8) * DIM + cc) =
                (uint32_t)__half_as_ushort(h2) | ((uint32_t)__half_as_ushort(h3) << 16);
        }
    }
}

// ======================= kernel: fused scores = exp(Q·K^T*scale) (causal, 1-term, 4-stage NK) =======================
__global__ __launch_bounds__(256) void scores_gemm() {
    if (blockIdx.x > blockIdx.y) return;     // fully-masked tile, exits immediately
    extern __shared__ char smem[];
    const int b = blockIdx.z, q0 = blockIdx.y * 128, k0 = blockIdx.x * 128;
    const size_t boff = (size_t)b * SEQ * DIM;
    float acc[4][4][4];
    gemm_f16<false, 4>(g_qh + boff + (size_t)q0 * DIM, DIM,
                       g_kh + boff + (size_t)k0 * DIM, DIM, DIM / 32, acc);
    const bool diag = (blockIdx.x == blockIdx.y);
    __half* ph = g_ph + (size_t)b * SEQ * SEQ;
    const int lane = threadIdx.x & 31, warp = threadIdx.x >> 5;
    const int g = lane >> 2, t = lane & 3, wm = warp >> 2, wn = warp & 3;
    const float scale = 0.03125f;

    float* red = reinterpret_cast<float*>(smem);
    float rs0[4], rs1[4];
#pragma unroll
    for (int mi = 0; mi < 4; mi++) { rs0[mi] = 0.f; rs1[mi] = 0.f; }

#pragma unroll
    for (int mi = 0; mi < 4; mi++) {
        const int r0 = q0 + wm * 64 + mi * 16 + g;
#pragma unroll
        for (int ni = 0; ni < 4; ni++) {
            const int cc = k0 + wn * 32 + ni * 8 + 2 * t;
            float e0 = __expf(acc[mi][ni][0] * scale);
            float e1 = __expf(acc[mi][ni][1] * scale);
            float e2 = __expf(acc[mi][ni][2] * scale);
            float e3 = __expf(acc[mi][ni][3] * scale);
            if (diag) {
                if (cc     > r0)     e0 = 0.f;
                if (cc + 1 > r0)     e1 = 0.f;
                if (cc     > r0 + 8) e2 = 0.f;
                if (cc + 1 > r0 + 8) e3 = 0.f;
            }
            __half p0 = __float2half_rn(e0), p1 = __float2half_rn(e1);
            __half p2 = __float2half_rn(e2), p3 = __float2half_rn(e3);
            *reinterpret_cast<uint32_t*>(ph + (size_t)r0 * SEQ + cc) =
                (uint32_t)__half_as_ushort(p0) | ((uint32_t)__half_as_ushort(p1) << 16);
            *reinterpret_cast<uint32_t*>(ph + (size_t)(r0 + 8) * SEQ + cc) =
                (uint32_t)__half_as_ushort(p2) | ((uint32_t)__half_as_ushort(p3) << 16);
            rs0[mi] += e0 + e1;
            rs1[mi] += e2 + e3;
        }
    }
#pragma unroll
    for (int mi = 0; mi < 4; mi++) {
        float s0 = rs0[mi], s1 = rs1[mi];
        s0 += __shfl_xor_sync(0xFFFFFFFFu, s0, 1);
        s0 += __shfl_xor_sync(0xFFFFFFFFu, s0, 2);
        s1 += __shfl_xor_sync(0xFFFFFFFFu, s1, 1);
        s1 += __shfl_xor_sync(0xFFFFFFFFu, s1, 2);
        if (t == 0) {
            const int lr = wm * 64 + mi * 16 + g;
            red[wn * 128 + lr]     = s0;
            red[wn * 128 + lr + 8] = s1;
        }
    }
    __syncthreads();
    if (threadIdx.x < 128) {
        float tot = red[threadIdx.x] + red[128 + threadIdx.x]
                  + red[256 + threadIdx.x] + red[384 + threadIdx.x];
        g_partial[b][blockIdx.x][q0 + threadIdx.x] = tot;
    }
}

// ======================= kernel: O = (P @ V) * rsuminv (fused rowsum, heavy-first order) =======================
__global__ __launch_bounds__(256) void pv_gemm(float* __restrict__ outp) {
    extern __shared__ char smem[];
    const int b = blockIdx.z, n0 = blockIdx.x * 128;
    const int qy = (int)gridDim.y - 1 - (int)blockIdx.y;   // heavy q-tiles launch first
    const int q0 = qy * 128;

    float* rsinv = reinterpret_cast<float*>(smem + PV_STAGES * PV_STAGE_B);
    if (threadIdx.x < 128) {
        const int q = q0 + threadIdx.x;
        const int nt = (q0 >> 7) + 1;
        float s = 0.f;
        for (int j = 0; j < nt; j++) s += g_partial[b][j][q];
        rsinv[threadIdx.x] = 1.f / s;
    }

    float acc[4][4][4];
    gemm_f16<true, PV_STAGES>(g_ph + (size_t)b * SEQ * SEQ + (size_t)q0 * SEQ, SEQ,
                              g_vh + (size_t)b * SEQ * DIM + n0, DIM,
                              (q0 + 128) / 32, acc);   // ends with __syncthreads -> rsinv visible
    float* out = outp + (size_t)b * SEQ * DIM;
    const int lane = threadIdx.x & 31, warp = threadIdx.x >> 5;
    const int g = lane >> 2, t = lane & 3, wm = warp >> 2, wn = warp & 3;
#pragma unroll
    for (int mi = 0; mi < 4; mi++) {
        const int lr = wm * 64 + mi * 16 + g;
        const int r0 = q0 + lr;
        const float i0 = rsinv[lr], i1 = rsinv[lr + 8];
#pragma unroll
        for (int ni = 0; ni < 4; ni++) {
            const int cc = n0 + wn * 32 + ni * 8 + 2 * t;
            *reinterpret_cast<float2*>(out + (size_t)r0 * DIM + cc) =
                make_float2(acc[mi][ni][0] * i0, acc[mi][ni][1] * i0);
            *reinterpret_cast<float2*>(out + (size_t)(r0 + 8) * DIM + cc) =
                make_float2(acc[mi][ni][2] * i1, acc[mi][ni][3] * i1);
        }
    }
}

// ======================= launch =======================
extern "C" void kernel_launch(void* const* d_in, const int* in_sizes, int n_in,
                              void* d_out, int out_size) {
    const float* x  = (const float*)d_in[0];
    const float* Wq = (const float*)d_in[1];
    const float* Wk = (const float*)d_in[2];
    const float* Wv = (const float*)d_in[3];
    float* out = (float*)d_out;

    cudaFuncSetAttribute(qkv_gemm,    cudaFuncAttributeMaxDynamicSharedMemorySize, SMEM_QKV);
    cudaFuncSetAttribute(scores_gemm, cudaFuncAttributeMaxDynamicSharedMemorySize, SMEM_SC);
    cudaFuncSetAttribute(pv_gemm,     cudaFuncAttributeMaxDynamicSharedMemorySize, SMEM_PV);

    const size_t total = XN + 3 * WN;
    split_all<<<(unsigned)(total / 1024), 256>>>(x, Wq, Wk, Wv);

    qkv_gemm<<<dim3(DIM / 128, MTOT / 128, 3), 256, SMEM_QKV>>>();
    scores_gemm<<<dim3(SEQ / 128, SEQ / 128, BATCH), 256, SMEM_SC>>>();
    pv_gemm<<<dim3(DIM / 128, SEQ / 128, BATCH), 256, SMEM_PV>>>(out);
}

// round 16
// speedup vs baseline: 2.0862x; 1.0690x over previous
#include <cuda_runtime.h>
#include <cuda_fp16.h>
#include <math.h>
#include <stdint.h>

#define BATCH 4
#define SEQ   2048
#define DIM   1024
#define MTOT  (BATCH * SEQ)   // 8192

// ======================= device scratch (no runtime alloc) =======================
__device__ __align__(128) __half g_xh[(size_t)MTOT * DIM];      // X fp16
__device__ __align__(128) __half g_wh[3][(size_t)DIM * DIM];    // W fp16 [din][dout]
__device__ __align__(128) __half g_qh[(size_t)MTOT * DIM];      // Q fp16
__device__ __align__(128) __half g_kh[(size_t)MTOT * DIM];      // K fp16
__device__ __align__(128) __half g_vh[(size_t)MTOT * DIM];      // V fp16
__device__ __align__(128) __half g_ph[(size_t)BATCH * SEQ * SEQ]; // unnorm probs
__device__ __align__(128) float  g_partial[BATCH][SEQ / 128][SEQ]; // rowsum partials

// ======================= PTX helpers (arch-agnostic, sm_80-era) =======================
__device__ __forceinline__ uint32_t smem_u32(const void* p) {
    uint32_t a;
    asm("{ .reg .u64 t; cvta.to.shared.u64 t, %1; cvt.u32.u64 %0, t; }" : "=r"(a) : "l"(p));
    return a;
}
__device__ __forceinline__ void cp16(uint32_t dst, const void* src) {
    asm volatile("cp.async.cg.shared.global [%0], [%1], 16;" :: "r"(dst), "l"(src));
}
__device__ __forceinline__ void cp_commit() { asm volatile("cp.async.commit_group;"); }
template<int N>
__device__ __forceinline__ void cp_wait() { asm volatile("cp.async.wait_group %0;" :: "n"(N)); }
template<int NSTAGES>
__device__ __forceinline__ void cp_wait_stage() {
    if constexpr (NSTAGES == 2)      cp_wait<0>();
    else if constexpr (NSTAGES == 3) cp_wait<1>();
    else                             cp_wait<2>();
}

__device__ __forceinline__ void ldsm4(uint32_t* r, uint32_t a) {
    asm volatile("ldmatrix.sync.aligned.m8n8.x4.shared.b16 {%0,%1,%2,%3}, [%4];"
                 : "=r"(r[0]), "=r"(r[1]), "=r"(r[2]), "=r"(r[3]) : "r"(a));
}
__device__ __forceinline__ void ldsm4t(uint32_t* r, uint32_t a) {
    asm volatile("ldmatrix.sync.aligned.m8n8.x4.trans.shared.b16 {%0,%1,%2,%3}, [%4];"
                 : "=r"(r[0]), "=r"(r[1]), "=r"(r[2]), "=r"(r[3]) : "r"(a));
}
__device__ __forceinline__ void mma_f16(float* c, const uint32_t* a, const uint32_t* b) {
    asm volatile(
        "mma.sync.aligned.m16n8k16.row.col.f32.f16.f16.f32 "
        "{%0,%1,%2,%3},{%4,%5,%6,%7},{%8,%9},{%0,%1,%2,%3};"
        : "+f"(c[0]), "+f"(c[1]), "+f"(c[2]), "+f"(c[3])
        : "r"(a[0]), "r"(a[1]), "r"(a[2]), "r"(a[3]), "r"(b[0]), "r"(b[1]));
}

// ======================= smem layouts (BK = 64) =======================
// A tile: 128 rows x 64 halves, padded stride 144 B -> 18432 B
// B KN:   64 k-rows x 128 halves, stride 272 B      -> 17408 B (ldsm.trans)
// B NK:   128 n-rows x 64 halves, stride 144 B      -> 18432 B (ldsm)
// KN stage 35840; NK stage 36864. 3 stages everywhere (2 CTAs/SM):
//   qkv/pv: 107520 (x2 = 215040), scores: 110592 (x2 = 221184) <= 227328 proven budget
#define A_TILE_B    18432
#define STAGE_KN    35840
#define STAGE_NK    36864
#define NST         3
#define SMEM_QKV    (NST * STAGE_KN)          // 107520
#define SMEM_SC     (NST * STAGE_NK)          // 110592
#define SMEM_PV     (NST * STAGE_KN + 512)    // 108032

// ======================= unified 1-term fp16 GEMM (128x128 tile, BK=64, 256 thr) =======================
// acc += A*B, fp32 accumulate.
// BKN=true : B stored [k][n] row-major (ldb=n-stride), ldmatrix.trans
// BKN=false: B stored [n][k] row-major (ldb=k-stride), ldmatrix
// One commit_group per loop iteration (empty at tail) keeps wait<k> accounting exact.
template<bool BKN>
__device__ __forceinline__ void gemm_f16(
    const __half* __restrict__ a, int lda,
    const __half* __restrict__ b, int ldb,
    int nchunks, float (&acc)[4][4][4])
{
    extern __shared__ char smem[];
    const uint32_t sb = smem_u32(smem);
    const int tid = threadIdx.x;
    const int lane = tid & 31, warp = tid >> 5;
    const int wm = warp >> 2, wn = warp & 3;
    constexpr int BT = BKN ? 17408 : 18432;
    constexpr int STAGE = A_TILE_B + BT;

#pragma unroll
    for (int mi = 0; mi < 4; mi++)
#pragma unroll
        for (int ni = 0; ni < 4; ni++)
#pragma unroll
            for (int k = 0; k < 4; k++) acc[mi][ni][k] = 0.f;

    auto load_chunk = [&](int s, int c) {
        const uint32_t base = sb + (uint32_t)s * STAGE;
        const uint32_t ah = base, bh = base + A_TILE_B;
        int i = tid;
#pragma unroll
        for (int j = 0; j < 4; j++, i += 256) {
            {   // A: 128 rows x 8 vec8 (64 halves)
                int row = i >> 3, cc = i & 7;
                size_t go = (size_t)row * lda + c * 64 + cc * 8;
                uint32_t so = (uint32_t)row * 144u + (uint32_t)cc * 16u;
                cp16(ah + so, a + go);
            }
            if (BKN) {  // B: 64 k-rows x 16 vec8 (128 halves)
                int row = i >> 4, cc = i & 15;
                size_t go = (size_t)(c * 64 + row) * ldb + cc * 8;
                uint32_t so = (uint32_t)row * 272u + (uint32_t)cc * 16u;
                cp16(bh + so, b + go);
            } else {    // B: 128 n-rows x 8 vec8 (64 halves)
                int row = i >> 3, cc = i & 7;
                size_t go = (size_t)row * ldb + c * 64 + cc * 8;
                uint32_t so = (uint32_t)row * 144u + (uint32_t)cc * 16u;
                cp16(bh + so, b + go);
            }
        }
        cp_commit();
    };

#pragma unroll
    for (int s = 0; s < NST - 1; s++)
        if (s < nchunks) load_chunk(s, s);

    for (int c = 0; c < nchunks; ++c) {
        cp_wait_stage<NST>();
        __syncthreads();
        const int cnext = c + NST - 1;
        if (cnext < nchunks) {
            int s = cnext; while (s >= NST) s -= NST;
            load_chunk(s, cnext);
        } else {
            cp_commit();
        }

        int s = c; while (s >= NST) s -= NST;
        const uint32_t base = sb + (uint32_t)s * STAGE;
        const uint32_t ah = base, bh = base + A_TILE_B;

#pragma unroll
        for (int ks = 0; ks < 4; ++ks) {
            uint32_t Ah[4][4], Bh[4][2];
            const uint32_t ao = (uint32_t)(wm * 64 + (lane & 15)) * 144u
                              + (uint32_t)(ks * 16 + (lane >> 4) * 8) * 2u;
#pragma unroll
            for (int mi = 0; mi < 4; mi++)
                ldsm4(Ah[mi], ah + ao + (uint32_t)(mi * 16) * 144u);
            if (BKN) {
                const uint32_t brow = (uint32_t)(ks * 16 + (lane & 15));
#pragma unroll
                for (int p = 0; p < 2; p++) {
                    const uint32_t bo = brow * 272u
                        + (uint32_t)(wn * 32 + p * 16 + (lane >> 4) * 8) * 2u;
                    uint32_t r[4];
                    ldsm4t(r, bh + bo);
                    Bh[2*p][0] = r[0]; Bh[2*p][1] = r[1];
                    Bh[2*p+1][0] = r[2]; Bh[2*p+1][1] = r[3];
                }
            } else {
                const uint32_t bcol2 = (uint32_t)(ks * 16 + ((lane >> 3) & 1) * 8) * 2u;
#pragma unroll
                for (int p = 0; p < 2; p++) {
                    const uint32_t brow = (uint32_t)(wn * 32 + p * 16 + (lane & 7) + ((lane >> 4) << 3));
                    const uint32_t bo = brow * 144u + bcol2;
                    uint32_t r[4];
                    ldsm4(r, bh + bo);
                    Bh[2*p][0] = r[0]; Bh[2*p][1] = r[1];
                    Bh[2*p+1][0] = r[2]; Bh[2*p+1][1] = r[3];
                }
            }
#pragma unroll
            for (int mi = 0; mi < 4; mi++)
#pragma unroll
                for (int ni = 0; ni < 4; ni++)
                    mma_f16(acc[mi][ni], Ah[mi], Bh[ni]);
        }
    }
    __syncthreads();
}

// ======================= kernel: convert fp32 -> fp16 (x + Wq + Wk + Wv) =======================
#define XN ((size_t)MTOT * DIM)          // 8388608
#define WN ((size_t)DIM * DIM)           // 1048576
__global__ __launch_bounds__(256) void split_all(const float* __restrict__ x,
                                                 const float* __restrict__ wq,
                                                 const float* __restrict__ wk,
                                                 const float* __restrict__ wv) {
    size_t i = ((size_t)blockIdx.x * 256 + threadIdx.x) * 4;
    const float* src;
    __half* hi;
    size_t off;
    if (i < XN) { src = x; off = i; hi = g_xh; }
    else {
        size_t j = i - XN;
        int w = (int)(j / WN);
        off = j - (size_t)w * WN;
        src = (w == 0) ? wq : (w == 1) ? wk : wv;
        hi = g_wh[w];
    }
    float4 v = *reinterpret_cast<const float4*>(src + off);
    __half h0 = __float2half_rn(v.x), h1 = __float2half_rn(v.y);
    __half h2 = __float2half_rn(v.z), h3 = __float2half_rn(v.w);
    uint32_t p0 = (uint32_t)__half_as_ushort(h0) | ((uint32_t)__half_as_ushort(h1) << 16);
    uint32_t p1 = (uint32_t)__half_as_ushort(h2) | ((uint32_t)__half_as_ushort(h3) << 16);
    *reinterpret_cast<uint2*>(hi + off) = make_uint2(p0, p1);
}

// ======================= kernel: QKV projection (1-term, 128x128 tile, BK=64 KN) =======================
__global__ __launch_bounds__(256) void qkv_gemm() {
    const int z = blockIdx.z, m0 = blockIdx.y * 128, n0 = blockIdx.x * 128;
    float acc[4][4][4];
    gemm_f16<true>(g_xh + (size_t)m0 * DIM, DIM, g_wh[z] + n0, DIM, DIM / 64, acc);
    const int lane = threadIdx.x & 31, warp = threadIdx.x >> 5;
    const int g = lane >> 2, t = lane & 3, wm = warp >> 2, wn = warp & 3;
    __half* dst = (z == 0) ? g_qh : (z == 1) ? g_kh : g_vh;
#pragma unroll
    for (int mi = 0; mi < 4; mi++) {
        const int r0 = m0 + wm * 64 + mi * 16 + g;
#pragma unroll
        for (int ni = 0; ni < 4; ni++) {
            const int cc = n0 + wn * 32 + ni * 8 + 2 * t;
            __half h0 = __float2half_rn(acc[mi][ni][0]);
            __half h1 = __float2half_rn(acc[mi][ni][1]);
            __half h2 = __float2half_rn(acc[mi][ni][2]);
            __half h3 = __float2half_rn(acc[mi][ni][3]);
            *reinterpret_cast<uint32_t*>(dst + (size_t)r0 * DIM + cc) =
                (uint32_t)__half_as_ushort(h0) | ((uint32_t)__half_as_ushort(h1) << 16);
            *reinterpret_cast<uint32_t*>(dst + (size_t)(r0 + 8) * DIM + cc) =
                (uint32_t)__half_as_ushort(h2) | ((uint32_t)__half_as_ushort(h3) << 16);
        }
    }
}

// ======================= kernel: fused scores = exp(Q·K^T*scale) (causal, 1-term, BK=64 NK) =======================
__global__ __launch_bounds__(256) void scores_gemm() {
    if (blockIdx.x > blockIdx.y) return;     // fully-masked tile, exits immediately
    extern __shared__ char smem[];
    const int b = blockIdx.z, q0 = blockIdx.y * 128, k0 = blockIdx.x * 128;
    const size_t boff = (size_t)b * SEQ * DIM;
    float acc[4][4][4];
    gemm_f16<false>(g_qh + boff + (size_t)q0 * DIM, DIM,
                    g_kh + boff + (size_t)k0 * DIM, DIM, DIM / 64, acc);
    const bool diag = (blockIdx.x == blockIdx.y);
    __half* ph = g_ph + (size_t)b * SEQ * SEQ;
    const int lane = threadIdx.x & 31, warp = threadIdx.x >> 5;
    const int g = lane >> 2, t = lane & 3, wm = warp >> 2, wn = warp & 3;
    const float scale = 0.03125f;

    float* red = reinterpret_cast<float*>(smem);
    float rs0[4], rs1[4];
#pragma unroll
    for (int mi = 0; mi < 4; mi++) { rs0[mi] = 0.f; rs1[mi] = 0.f; }

#pragma unroll
    for (int mi = 0; mi < 4; mi++) {
        const int r0 = q0 + wm * 64 + mi * 16 + g;
#pragma unroll
        for (int ni = 0; ni < 4; ni++) {
            const int cc = k0 + wn * 32 + ni * 8 + 2 * t;
            float e0 = __expf(acc[mi][ni][0] * scale);
            float e1 = __expf(acc[mi][ni][1] * scale);
            float e2 = __expf(acc[mi][ni][2] * scale);
            float e3 = __expf(acc[mi][ni][3] * scale);
            if (diag) {
                if (cc     > r0)     e0 = 0.f;
                if (cc + 1 > r0)     e1 = 0.f;
                if (cc     > r0 + 8) e2 = 0.f;
                if (cc + 1 > r0 + 8) e3 = 0.f;
            }
            __half p0 = __float2half_rn(e0), p1 = __float2half_rn(e1);
            __half p2 = __float2half_rn(e2), p3 = __float2half_rn(e3);
            *reinterpret_cast<uint32_t*>(ph + (size_t)r0 * SEQ + cc) =
                (uint32_t)__half_as_ushort(p0) | ((uint32_t)__half_as_ushort(p1) << 16);
            *reinterpret_cast<uint32_t*>(ph + (size_t)(r0 + 8) * SEQ + cc) =
                (uint32_t)__half_as_ushort(p2) | ((uint32_t)__half_as_ushort(p3) << 16);
            rs0[mi] += e0 + e1;
            rs1[mi] += e2 + e3;
        }
    }
#pragma unroll
    for (int mi = 0; mi < 4; mi++) {
        float s0 = rs0[mi], s1 = rs1[mi];
        s0 += __shfl_xor_sync(0xFFFFFFFFu, s0, 1);
        s0 += __shfl_xor_sync(0xFFFFFFFFu, s0, 2);
        s1 += __shfl_xor_sync(0xFFFFFFFFu, s1, 1);
        s1 += __shfl_xor_sync(0xFFFFFFFFu, s1, 2);
        if (t == 0) {
            const int lr = wm * 64 + mi * 16 + g;
            red[wn * 128 + lr]     = s0;
            red[wn * 128 + lr + 8] = s1;
        }
    }
    __syncthreads();
    if (threadIdx.x < 128) {
        float tot = red[threadIdx.x] + red[128 + threadIdx.x]
                  + red[256 + threadIdx.x] + red[384 + threadIdx.x];
        g_partial[b][blockIdx.x][q0 + threadIdx.x] = tot;
    }
}

// ======================= kernel: O = (P @ V) * rsuminv (fused rowsum, heavy-first order) =======================
__global__ __launch_bounds__(256) void pv_gemm(float* __restrict__ outp) {
    extern __shared__ char smem[];
    const int b = blockIdx.z, n0 = blockIdx.x * 128;
    const int qy = (int)gridDim.y - 1 - (int)blockIdx.y;   // heavy q-tiles launch first
    const int q0 = qy * 128;

    float* rsinv = reinterpret_cast<float*>(smem + NST * STAGE_KN);
    if (threadIdx.x < 128) {
        const int q = q0 + threadIdx.x;
        const int nt = (q0 >> 7) + 1;
        float s = 0.f;
        for (int j = 0; j < nt; j++) s += g_partial[b][j][q];
        rsinv[threadIdx.x] = 1.f / s;
    }

    float acc[4][4][4];
    gemm_f16<true>(g_ph + (size_t)b * SEQ * SEQ + (size_t)q0 * SEQ, SEQ,
                   g_vh + (size_t)b * SEQ * DIM + n0, DIM,
                   (q0 + 128) / 64, acc);   // ends with __syncthreads -> rsinv visible
    float* out = outp + (size_t)b * SEQ * DIM;
    const int lane = threadIdx.x & 31, warp = threadIdx.x >> 5;
    const int g = lane >> 2, t = lane & 3, wm = warp >> 2, wn = warp & 3;
#pragma unroll
    for (int mi = 0; mi < 4; mi++) {
        const int lr = wm * 64 + mi * 16 + g;
        const int r0 = q0 + lr;
        const float i0 = rsinv[lr], i1 = rsinv[lr + 8];
#pragma unroll
        for (int ni = 0; ni < 4; ni++) {
            const int cc = n0 + wn * 32 + ni * 8 + 2 * t;
            *reinterpret_cast<float2*>(out + (size_t)r0 * DIM + cc) =
                make_float2(acc[mi][ni][0] * i0, acc[mi][ni][1] * i0);
            *reinterpret_cast<float2*>(out + (size_t)(r0 + 8) * DIM + cc) =
                make_float2(acc[mi][ni][2] * i1, acc[mi][ni][3] * i1);
        }
    }
}

// ======================= launch =======================
extern "C" void kernel_launch(void* const* d_in, const int* in_sizes, int n_in,
                              void* d_out, int out_size) {
    const float* x  = (const float*)d_in[0];
    const float* Wq = (const float*)d_in[1];
    const float* Wk = (const float*)d_in[2];
    const float* Wv = (const float*)d_in[3];
    float* out = (float*)d_out;

    cudaFuncSetAttribute(qkv_gemm,    cudaFuncAttributeMaxDynamicSharedMemorySize, SMEM_QKV);
    cudaFuncSetAttribute(scores_gemm, cudaFuncAttributeMaxDynamicSharedMemorySize, SMEM_SC);
    cudaFuncSetAttribute(pv_gemm,     cudaFuncAttributeMaxDynamicSharedMemorySize, SMEM_PV);

    const size_t total = XN + 3 * WN;
    split_all<<<(unsigned)(total / 1024), 256>>>(x, Wq, Wk, Wv);

    qkv_gemm<<<dim3(DIM / 128, MTOT / 128, 3), 256, SMEM_QKV>>>();
    scores_gemm<<<dim3(SEQ / 128, SEQ / 128, BATCH), 256, SMEM_SC>>>();
    pv_gemm<<<dim3(DIM / 128, SEQ / 128, BATCH), 256, SMEM_PV>>>(out);
}

// round 17
// speedup vs baseline: 2.0998x; 1.0065x over previous
#include <cuda_runtime.h>
#include <cuda_fp16.h>
#include <math.h>
#include <stdint.h>

#define BATCH 4
#define SEQ   2048
#define DIM   1024
#define MTOT  (BATCH * SEQ)   // 8192

// ======================= device scratch (no runtime alloc) =======================
__device__ __align__(128) __half g_xh[(size_t)MTOT * DIM];      // X fp16
__device__ __align__(128) __half g_wh[3][(size_t)DIM * DIM];    // W fp16 [din][dout]
__device__ __align__(128) __half g_qh[(size_t)MTOT * DIM];      // Q fp16
__device__ __align__(128) __half g_kh[(size_t)MTOT * DIM];      // K fp16
__device__ __align__(128) __half g_vh[(size_t)MTOT * DIM];      // V fp16
__device__ __align__(128) __half g_ph[(size_t)BATCH * SEQ * SEQ]; // unnorm probs
__device__ __align__(128) float  g_partial[BATCH][SEQ / 128][SEQ]; // rowsum partials

// ======================= PTX helpers (arch-agnostic, sm_80-era) =======================
__device__ __forceinline__ uint32_t smem_u32(const void* p) {
    uint32_t a;
    asm("{ .reg .u64 t; cvta.to.shared.u64 t, %1; cvt.u32.u64 %0, t; }" : "=r"(a) : "l"(p));
    return a;
}
__device__ __forceinline__ void cp16(uint32_t dst, const void* src) {
    asm volatile("cp.async.cg.shared.global [%0], [%1], 16;" :: "r"(dst), "l"(src));
}
__device__ __forceinline__ void cp_commit() { asm volatile("cp.async.commit_group;"); }
template<int N>
__device__ __forceinline__ void cp_wait() { asm volatile("cp.async.wait_group %0;" :: "n"(N)); }

__device__ __forceinline__ void ldsm4(uint32_t* r, uint32_t a) {
    asm volatile("ldmatrix.sync.aligned.m8n8.x4.shared.b16 {%0,%1,%2,%3}, [%4];"
                 : "=r"(r[0]), "=r"(r[1]), "=r"(r[2]), "=r"(r[3]) : "r"(a));
}
__device__ __forceinline__ void ldsm4t(uint32_t* r, uint32_t a) {
    asm volatile("ldmatrix.sync.aligned.m8n8.x4.trans.shared.b16 {%0,%1,%2,%3}, [%4];"
                 : "=r"(r[0]), "=r"(r[1]), "=r"(r[2]), "=r"(r[3]) : "r"(a));
}
__device__ __forceinline__ void mma_f16(float* c, const uint32_t* a, const uint32_t* b) {
    asm volatile(
        "mma.sync.aligned.m16n8k16.row.col.f32.f16.f16.f32 "
        "{%0,%1,%2,%3},{%4,%5,%6,%7},{%8,%9},{%0,%1,%2,%3};"
        : "+f"(c[0]), "+f"(c[1]), "+f"(c[2]), "+f"(c[3])
        : "r"(a[0]), "r"(a[1]), "r"(a[2]), "r"(a[3]), "r"(b[0]), "r"(b[1]));
}

// ======================= smem layouts (BK = 64) =======================
// A tile: 128 rows x 64 halves, padded stride 144 B -> 18432 B
// B KN:   64 k-rows x 128 halves, stride 272 B      -> 17408 B (ldsm.trans)
// B NK:   128 n-rows x 64 halves, stride 144 B      -> 18432 B (ldsm)
// KN stage 35840; NK stage 36864. 3 stages everywhere (2 CTAs/SM by smem).
#define A_TILE_B    18432
#define NST         3
#define SMEM_QKV    (NST * 35840)          // 107520
#define SMEM_SC     (NST * 36864)          // 110592
#define SMEM_PV     (NST * 35840 + 512)    // 108032

// ======================= unified 1-term fp16 GEMM (128x128 tile, BK=64, 512 thr, 4x4 warps) =======================
// Warp tile 32(m) x 32(n): mi<2 (m16), ni<4 (n8). acc[2][4][4].
// BKN=true : B stored [k][n] row-major (ldb=n-stride), ldmatrix.trans
// BKN=false: B stored [n][k] row-major (ldb=k-stride), ldmatrix
// One commit_group per loop iteration (empty at tail) keeps wait<1> accounting exact.
template<bool BKN>
__device__ __forceinline__ void gemm_f16(
    const __half* __restrict__ a, int lda,
    const __half* __restrict__ b, int ldb,
    int nchunks, float (&acc)[2][4][4])
{
    extern __shared__ char smem[];
    const uint32_t sb = smem_u32(smem);
    const int tid = threadIdx.x;
    const int lane = tid & 31, warp = tid >> 5;
    const int wm = warp >> 2, wn = warp & 3;          // 4 x 4 warp grid
    constexpr int BT = BKN ? 17408 : 18432;
    constexpr int STAGE = A_TILE_B + BT;

#pragma unroll
    for (int mi = 0; mi < 2; mi++)
#pragma unroll
        for (int ni = 0; ni < 4; ni++)
#pragma unroll
            for (int k = 0; k < 4; k++) acc[mi][ni][k] = 0.f;

    auto load_chunk = [&](int s, int c) {
        const uint32_t base = sb + (uint32_t)s * STAGE;
        const uint32_t ah = base, bh = base + A_TILE_B;
        int i = tid;
#pragma unroll
        for (int j = 0; j < 2; j++, i += 512) {
            {   // A: 128 rows x 8 vec8 (64 halves) = 1024 vec8
                int row = i >> 3, cc = i & 7;
                size_t go = (size_t)row * lda + c * 64 + cc * 8;
                uint32_t so = (uint32_t)row * 144u + (uint32_t)cc * 16u;
                cp16(ah + so, a + go);
            }
            if (BKN) {  // B: 64 k-rows x 16 vec8 = 1024 vec8
                int row = i >> 4, cc = i & 15;
                size_t go = (size_t)(c * 64 + row) * ldb + cc * 8;
                uint32_t so = (uint32_t)row * 272u + (uint32_t)cc * 16u;
                cp16(bh + so, b + go);
            } else {    // B: 128 n-rows x 8 vec8 = 1024 vec8
                int row = i >> 3, cc = i & 7;
                size_t go = (size_t)row * ldb + c * 64 + cc * 8;
                uint32_t so = (uint32_t)row * 144u + (uint32_t)cc * 16u;
                cp16(bh + so, b + go);
            }
        }
        cp_commit();
    };

#pragma unroll
    for (int s = 0; s < NST - 1; s++)
        if (s < nchunks) load_chunk(s, s);

    for (int c = 0; c < nchunks; ++c) {
        cp_wait<1>();
        __syncthreads();
        const int cnext = c + NST - 1;
        if (cnext < nchunks) {
            int s = cnext; while (s >= NST) s -= NST;
            load_chunk(s, cnext);
        } else {
            cp_commit();
        }

        int s = c; while (s >= NST) s -= NST;
        const uint32_t base = sb + (uint32_t)s * STAGE;
        const uint32_t ah = base, bh = base + A_TILE_B;

#pragma unroll
        for (int ks = 0; ks < 4; ++ks) {
            uint32_t Ah[2][4], Bh[4][2];
            const uint32_t ao = (uint32_t)(wm * 32 + (lane & 15)) * 144u
                              + (uint32_t)(ks * 16 + (lane >> 4) * 8) * 2u;
#pragma unroll
            for (int mi = 0; mi < 2; mi++)
                ldsm4(Ah[mi], ah + ao + (uint32_t)(mi * 16) * 144u);
            if (BKN) {
                const uint32_t brow = (uint32_t)(ks * 16 + (lane & 15));
#pragma unroll
                for (int p = 0; p < 2; p++) {
                    const uint32_t bo = brow * 272u
                        + (uint32_t)(wn * 32 + p * 16 + (lane >> 4) * 8) * 2u;
                    uint32_t r[4];
                    ldsm4t(r, bh + bo);
                    Bh[2*p][0] = r[0]; Bh[2*p][1] = r[1];
                    Bh[2*p+1][0] = r[2]; Bh[2*p+1][1] = r[3];
                }
            } else {
                const uint32_t bcol2 = (uint32_t)(ks * 16 + ((lane >> 3) & 1) * 8) * 2u;
#pragma unroll
                for (int p = 0; p < 2; p++) {
                    const uint32_t brow = (uint32_t)(wn * 32 + p * 16 + (lane & 7) + ((lane >> 4) << 3));
                    const uint32_t bo = brow * 144u + bcol2;
                    uint32_t r[4];
                    ldsm4(r, bh + bo);
                    Bh[2*p][0] = r[0]; Bh[2*p][1] = r[1];
                    Bh[2*p+1][0] = r[2]; Bh[2*p+1][1] = r[3];
                }
            }
#pragma unroll
            for (int mi = 0; mi < 2; mi++)
#pragma unroll
                for (int ni = 0; ni < 4; ni++)
                    mma_f16(acc[mi][ni], Ah[mi], Bh[ni]);
        }
    }
    __syncthreads();
}

// ======================= kernel: convert fp32 -> fp16 (x + Wq + Wk + Wv) =======================
#define XN ((size_t)MTOT * DIM)          // 8388608
#define WN ((size_t)DIM * DIM)           // 1048576
__global__ __launch_bounds__(256) void split_all(const float* __restrict__ x,
                                                 const float* __restrict__ wq,
                                                 const float* __restrict__ wk,
                                                 const float* __restrict__ wv) {
    size_t i = ((size_t)blockIdx.x * 256 + threadIdx.x) * 4;
    const float* src;
    __half* hi;
    size_t off;
    if (i < XN) { src = x; off = i; hi = g_xh; }
    else {
        size_t j = i - XN;
        int w = (int)(j / WN);
        off = j - (size_t)w * WN;
        src = (w == 0) ? wq : (w == 1) ? wk : wv;
        hi = g_wh[w];
    }
    float4 v = *reinterpret_cast<const float4*>(src + off);
    __half h0 = __float2half_rn(v.x), h1 = __float2half_rn(v.y);
    __half h2 = __float2half_rn(v.z), h3 = __float2half_rn(v.w);
    uint32_t p0 = (uint32_t)__half_as_ushort(h0) | ((uint32_t)__half_as_ushort(h1) << 16);
    uint32_t p1 = (uint32_t)__half_as_ushort(h2) | ((uint32_t)__half_as_ushort(h3) << 16);
    *reinterpret_cast<uint2*>(hi + off) = make_uint2(p0, p1);
}

// ======================= kernel: QKV projection (1-term, 128x128 tile, BK=64 KN, 512 thr) =======================
__global__ __launch_bounds__(512, 2) void qkv_gemm() {
    const int z = blockIdx.z, m0 = blockIdx.y * 128, n0 = blockIdx.x * 128;
    float acc[2][4][4];
    gemm_f16<true>(g_xh + (size_t)m0 * DIM, DIM, g_wh[z] + n0, DIM, DIM / 64, acc);
    const int lane = threadIdx.x & 31, warp = threadIdx.x >> 5;
    const int g = lane >> 2, t = lane & 3, wm = warp >> 2, wn = warp & 3;
    __half* dst = (z == 0) ? g_qh : (z == 1) ? g_kh : g_vh;
#pragma unroll
    for (int mi = 0; mi < 2; mi++) {
        const int r0 = m0 + wm * 32 + mi * 16 + g;
#pragma unroll
        for (int ni = 0; ni < 4; ni++) {
            const int cc = n0 + wn * 32 + ni * 8 + 2 * t;
            __half h0 = __float2half_rn(acc[mi][ni][0]);
            __half h1 = __float2half_rn(acc[mi][ni][1]);
            __half h2 = __float2half_rn(acc[mi][ni][2]);
            __half h3 = __float2half_rn(acc[mi][ni][3]);
            *reinterpret_cast<uint32_t*>(dst + (size_t)r0 * DIM + cc) =
                (uint32_t)__half_as_ushort(h0) | ((uint32_t)__half_as_ushort(h1) << 16);
            *reinterpret_cast<uint32_t*>(dst + (size_t)(r0 + 8) * DIM + cc) =
                (uint32_t)__half_as_ushort(h2) | ((uint32_t)__half_as_ushort(h3) << 16);
        }
    }
}

// ======================= kernel: fused scores = exp(Q·K^T*scale) (causal, BK=64 NK, 512 thr) =======================
__global__ __launch_bounds__(512, 2) void scores_gemm() {
    if (blockIdx.x > blockIdx.y) return;     // fully-masked tile, exits immediately
    extern __shared__ char smem[];
    const int b = blockIdx.z, q0 = blockIdx.y * 128, k0 = blockIdx.x * 128;
    const size_t boff = (size_t)b * SEQ * DIM;
    float acc[2][4][4];
    gemm_f16<false>(g_qh + boff + (size_t)q0 * DIM, DIM,
                    g_kh + boff + (size_t)k0 * DIM, DIM, DIM / 64, acc);
    const bool diag = (blockIdx.x == blockIdx.y);
    __half* ph = g_ph + (size_t)b * SEQ * SEQ;
    const int lane = threadIdx.x & 31, warp = threadIdx.x >> 5;
    const int g = lane >> 2, t = lane & 3, wm = warp >> 2, wn = warp & 3;
    const float scale = 0.03125f;

    float* red = reinterpret_cast<float*>(smem);   // [4 wn][128 rows]
    float rs[2];
    rs[0] = 0.f; rs[1] = 0.f;

#pragma unroll
    for (int mi = 0; mi < 2; mi++) {
        const int r0 = q0 + wm * 32 + mi * 16 + g;
        float rlow = 0.f, rhigh = 0.f;
#pragma unroll
        for (int ni = 0; ni < 4; ni++) {
            const int cc = k0 + wn * 32 + ni * 8 + 2 * t;
            float e0 = __expf(acc[mi][ni][0] * scale);
            float e1 = __expf(acc[mi][ni][1] * scale);
            float e2 = __expf(acc[mi][ni][2] * scale);
            float e3 = __expf(acc[mi][ni][3] * scale);
            if (diag) {
                if (cc     > r0)     e0 = 0.f;
                if (cc + 1 > r0)     e1 = 0.f;
                if (cc     > r0 + 8) e2 = 0.f;
                if (cc + 1 > r0 + 8) e3 = 0.f;
            }
            __half p0 = __float2half_rn(e0), p1 = __float2half_rn(e1);
            __half p2 = __float2half_rn(e2), p3 = __float2half_rn(e3);
            *reinterpret_cast<uint32_t*>(ph + (size_t)r0 * SEQ + cc) =
                (uint32_t)__half_as_ushort(p0) | ((uint32_t)__half_as_ushort(p1) << 16);
            *reinterpret_cast<uint32_t*>(ph + (size_t)(r0 + 8) * SEQ + cc) =
                (uint32_t)__half_as_ushort(p2) | ((uint32_t)__half_as_ushort(p3) << 16);
            rlow  += e0 + e1;
            rhigh += e2 + e3;
        }
        // reduce across t (lane&3)
        rlow  += __shfl_xor_sync(0xFFFFFFFFu, rlow, 1);
        rlow  += __shfl_xor_sync(0xFFFFFFFFu, rlow, 2);
        rhigh += __shfl_xor_sync(0xFFFFFFFFu, rhigh, 1);
        rhigh += __shfl_xor_sync(0xFFFFFFFFu, rhigh, 2);
        if (t == 0) {
            const int lr = wm * 32 + mi * 16 + g;
            red[wn * 128 + lr]     = rlow;
            red[wn * 128 + lr + 8] = rhigh;
        }
        rs[mi] = 0.f;  // (silence unused warning pattern)
    }
    __syncthreads();
    if (threadIdx.x < 128) {
        float tot = red[threadIdx.x] + red[128 + threadIdx.x]
                  + red[256 + threadIdx.x] + red[384 + threadIdx.x];
        g_partial[b][blockIdx.x][q0 + threadIdx.x] = tot;
    }
}

// ======================= kernel: O = (P @ V) * rsuminv (fused rowsum, heavy-first, 512 thr) =======================
__global__ __launch_bounds__(512, 2) void pv_gemm(float* __restrict__ outp) {
    extern __shared__ char smem[];
    const int b = blockIdx.z, n0 = blockIdx.x * 128;
    const int qy = (int)gridDim.y - 1 - (int)blockIdx.y;   // heavy q-tiles launch first
    const int q0 = qy * 128;

    float* rsinv = reinterpret_cast<float*>(smem + NST * 35840);
    if (threadIdx.x < 128) {
        const int q = q0 + threadIdx.x;
        const int nt = (q0 >> 7) + 1;
        float s = 0.f;
        for (int j = 0; j < nt; j++) s += g_partial[b][j][q];
        rsinv[threadIdx.x] = 1.f / s;
    }

    float acc[2][4][4];
    gemm_f16<true>(g_ph + (size_t)b * SEQ * SEQ + (size_t)q0 * SEQ, SEQ,
                   g_vh + (size_t)b * SEQ * DIM + n0, DIM,
                   (q0 + 128) / 64, acc);   // ends with __syncthreads -> rsinv visible
    float* out = outp + (size_t)b * SEQ * DIM;
    const int lane = threadIdx.x & 31, warp = threadIdx.x >> 5;
    const int g = lane >> 2, t = lane & 3, wm = warp >> 2, wn = warp & 3;
#pragma unroll
    for (int mi = 0; mi < 2; mi++) {
        const int lr = wm * 32 + mi * 16 + g;
        const int r0 = q0 + lr;
        const float i0 = rsinv[lr], i1 = rsinv[lr + 8];
#pragma unroll
        for (int ni = 0; ni < 4; ni++) {
            const int cc = n0 + wn * 32 + ni * 8 + 2 * t;
            *reinterpret_cast<float2*>(out + (size_t)r0 * DIM + cc) =
                make_float2(acc[mi][ni][0] * i0, acc[mi][ni][1] * i0);
            *reinterpret_cast<float2*>(out + (size_t)(r0 + 8) * DIM + cc) =
                make_float2(acc[mi][ni][2] * i1, acc[mi][ni][3] * i1);
        }
    }
}

// ======================= launch =======================
extern "C" void kernel_launch(void* const* d_in, const int* in_sizes, int n_in,
                              void* d_out, int out_size) {
    const float* x  = (const float*)d_in[0];
    const float* Wq = (const float*)d_in[1];
    const float* Wk = (const float*)d_in[2];
    const float* Wv = (const float*)d_in[3];
    float* out = (float*)d_out;

    cudaFuncSetAttribute(qkv_gemm,    cudaFuncAttributeMaxDynamicSharedMemorySize, SMEM_QKV);
    cudaFuncSetAttribute(scores_gemm, cudaFuncAttributeMaxDynamicSharedMemorySize, SMEM_SC);
    cudaFuncSetAttribute(pv_gemm,     cudaFuncAttributeMaxDynamicSharedMemorySize, SMEM_PV);

    const size_t total = XN + 3 * WN;
    split_all<<<(unsigned)(total / 1024), 256>>>(x, Wq, Wk, Wv);

    qkv_gemm<<<dim3(DIM / 128, MTOT / 128, 3), 512, SMEM_QKV>>>();
    scores_gemm<<<dim3(SEQ / 128, SEQ / 128, BATCH), 512, SMEM_SC>>>();
    pv_gemm<<<dim3(DIM / 128, SEQ / 128, BATCH), 512, SMEM_PV>>>(out);
}